// round 3
// baseline (speedup 1.0000x reference)
#include <cuda_runtime.h>
#include <math.h>

#define BB      16
#define SS      1024
#define HH      1024
#define HX4     4096
#define NSPAN   32
#define NHEADS  16
#define DHEAD   64
#define NCLS    5
#define NCTA    128
#define UPC     8
#define WPAD    1028

// ---------------- device scratch ----------------
__device__ float g_gates[(size_t)BB * SS * HX4];
__device__ float g_enc  [(size_t)BB * SS * HH];
__device__ float g_h    [2][BB * HH];
__device__ volatile int g_flags[NCTA];
__device__ float g_pool [BB * NSPAN * HH];
__device__ float g_q    [BB * NSPAN * HH];
__device__ float g_k    [BB * NSPAN * HH];
__device__ float g_v    [BB * NSPAN * HH];
__device__ float g_ctx  [BB * NSPAN * HH];
__device__ float g_wo   [BB * NSPAN * HH];
__device__ float g_attn [BB * NSPAN * HH];

// ============ fp32 GEMM: C[M,N] = A[M,K] @ W[N,K]^T + b1 (+ b2) ============
// grid (ceil(N/128), M/128), 256 threads. Requires M%128==0, K%8==0.
__global__ void sgemm_nt(const float* __restrict__ A, const float* __restrict__ W,
                         const float* __restrict__ b1, const float* __restrict__ b2,
                         float* __restrict__ C, int M, int N, int K)
{
    __shared__ float As[8][128];
    __shared__ float Ws[8][132];
    const int tid = threadIdx.x;
    const int n0 = blockIdx.x * 128, m0 = blockIdx.y * 128;
    const int lr = tid >> 1, lk = (tid & 1) << 2;
    const int tx = tid & 15, ty = tid >> 4;

    float acc[8][8];
#pragma unroll
    for (int i = 0; i < 8; i++)
#pragma unroll
        for (int j = 0; j < 8; j++) acc[i][j] = 0.f;

    const float* Arow = A + (size_t)(m0 + lr) * K + lk;
    const int wn = n0 + lr;
    const bool wok = (wn < N);
    const float* Wrow = W + (size_t)(wok ? wn : 0) * K + lk;

    for (int k0 = 0; k0 < K; k0 += 8) {
        float4 av = *(const float4*)(Arow + k0);
        float4 wv = make_float4(0.f, 0.f, 0.f, 0.f);
        if (wok) wv = *(const float4*)(Wrow + k0);
        As[lk + 0][lr] = av.x; As[lk + 1][lr] = av.y;
        As[lk + 2][lr] = av.z; As[lk + 3][lr] = av.w;
        Ws[lk + 0][lr] = wv.x; Ws[lk + 1][lr] = wv.y;
        Ws[lk + 2][lr] = wv.z; Ws[lk + 3][lr] = wv.w;
        __syncthreads();
#pragma unroll
        for (int kk = 0; kk < 8; kk++) {
            float a[8], w[8];
#pragma unroll
            for (int i = 0; i < 8; i++) a[i] = As[kk][ty * 8 + i];
#pragma unroll
            for (int j = 0; j < 8; j++) w[j] = Ws[kk][tx * 8 + j];
#pragma unroll
            for (int i = 0; i < 8; i++)
#pragma unroll
                for (int j = 0; j < 8; j++) acc[i][j] += a[i] * w[j];
        }
        __syncthreads();
    }
#pragma unroll
    for (int i = 0; i < 8; i++) {
        const int m = m0 + ty * 8 + i;
#pragma unroll
        for (int j = 0; j < 8; j++) {
            const int n = n0 + tx * 8 + j;
            if (n < N) {
                float bias = b1[n];
                if (b2) bias += b2[n];
                C[(size_t)m * N + n] = acc[i][j] + bias;
            }
        }
    }
}

// ============ persistent LSTM: 128 CTAs x 128 threads ============
__global__ void __launch_bounds__(128, 1)
lstm_kernel(const float* __restrict__ Whh)
{
    extern __shared__ float sm[];
    float* Wsh  = sm;                       // [32][WPAD]
    float* hsh  = Wsh + 32 * WPAD;          // [16][1024]
    float* gbuf = hsh + 16 * 1024;          // [32][17]
    float* cst  = gbuf + 32 * 17;           // [128]

    const int tid = threadIdx.x;
    const int cta = blockIdx.x;

    for (int i = tid; i < 32 * 256; i += 128) {
        const int rr = i >> 8, c4 = (i & 255) << 2;
        const int gg = rr >> 3, uu = rr & 7;
        const int j = gg * 1024 + cta * UPC + uu;
        *(float4*)(Wsh + rr * WPAD + c4) = *(const float4*)(Whh + (size_t)j * HH + c4);
    }
    cst[tid] = 0.f;
    const int base = g_flags[cta];
    __syncthreads();

    const int r  = tid & 31;
    const int bq = tid >> 5;
    const float4* wrow = (const float4*)(Wsh + r * WPAD);
    const float4* hr0 = (const float4*)(hsh + (bq * 4 + 0) * 1024);
    const float4* hr1 = (const float4*)(hsh + (bq * 4 + 1) * 1024);
    const float4* hr2 = (const float4*)(hsh + (bq * 4 + 2) * 1024);
    const float4* hr3 = (const float4*)(hsh + (bq * 4 + 3) * 1024);
    const int gg = r >> 3, uu = r & 7;
    const int jrow = gg * 1024 + cta * UPC + uu;
    const int su = tid & 7, sb = tid >> 3;

    for (int t = 0; t < SS; t++) {
        float a0 = 0.f, a1 = 0.f, a2 = 0.f, a3 = 0.f;
        if (t > 0) {
            if (tid < 32) {
                const int tgt = base + t;
                for (;;) {
                    bool ok = (g_flags[tid] >= tgt) && (g_flags[tid + 32] >= tgt) &&
                              (g_flags[tid + 64] >= tgt) && (g_flags[tid + 96] >= tgt);
                    if (__all_sync(0xffffffffu, ok)) break;
                    __nanosleep(64);
                }
            }
            __syncthreads();
            __threadfence();
            const float* hsrc = g_h[t & 1];
            for (int i = tid; i < 16 * 256; i += 128) {
                const int b2 = i >> 8, c4 = (i & 255) << 2;
                *(float4*)(hsh + b2 * 1024 + c4) = __ldcg((const float4*)(hsrc + b2 * 1024 + c4));
            }
            __syncthreads();
#pragma unroll 4
            for (int k4 = 0; k4 < 256; k4++) {
                const float4 w = wrow[k4];
                const float4 x0 = hr0[k4], x1 = hr1[k4], x2 = hr2[k4], x3 = hr3[k4];
                a0 += w.x*x0.x + w.y*x0.y + w.z*x0.z + w.w*x0.w;
                a1 += w.x*x1.x + w.y*x1.y + w.z*x1.z + w.w*x1.w;
                a2 += w.x*x2.x + w.y*x2.y + w.z*x2.z + w.w*x2.w;
                a3 += w.x*x3.x + w.y*x3.y + w.z*x3.z + w.w*x3.w;
            }
        }
        const size_t gb = (size_t)t * HX4 + jrow;
        gbuf[r * 17 + (bq*4+0)] = a0 + g_gates[(size_t)(bq*4+0) * SS * HX4 + gb];
        gbuf[r * 17 + (bq*4+1)] = a1 + g_gates[(size_t)(bq*4+1) * SS * HX4 + gb];
        gbuf[r * 17 + (bq*4+2)] = a2 + g_gates[(size_t)(bq*4+2) * SS * HX4 + gb];
        gbuf[r * 17 + (bq*4+3)] = a3 + g_gates[(size_t)(bq*4+3) * SS * HX4 + gb];
        __syncthreads();
        {
            const float iv = gbuf[(0*8+su)*17 + sb];
            const float fv = gbuf[(1*8+su)*17 + sb];
            const float gv = gbuf[(2*8+su)*17 + sb];
            const float ov = gbuf[(3*8+su)*17 + sb];
            const float ig = 1.f / (1.f + expf(-iv));
            const float fg = 1.f / (1.f + expf(-fv));
            const float og = 1.f / (1.f + expf(-ov));
            const float c = fg * cst[tid] + ig * tanhf(gv);
            cst[tid] = c;
            const float h = og * tanhf(c);
            const int unit = cta * UPC + su;
            g_h[(t + 1) & 1][sb * 1024 + unit] = h;
            g_enc[((size_t)sb * SS + t) * HH + unit] = h;
        }
        __threadfence();
        __syncthreads();
        if (tid == 0) g_flags[cta] = base + t + 1;
    }
}

// ============ block reduction helper (256 threads) ============
__device__ __forceinline__ float blk_sum256(float v, float* red)
{
#pragma unroll
    for (int o = 16; o > 0; o >>= 1) v += __shfl_down_sync(0xffffffffu, v, o);
    const int tid = threadIdx.x;
    if ((tid & 31) == 0) red[tid >> 5] = v;
    __syncthreads();
    float s;
    if (tid < 32) {
        float x = (tid < 8) ? red[tid] : 0.f;
#pragma unroll
        for (int o = 4; o > 0; o >>= 1) x += __shfl_down_sync(0xffffffffu, x, o);
        if (tid == 0) red[0] = x;
    }
    __syncthreads();
    s = red[0];
    __syncthreads();
    return s;
}

// ============ span mean-pool + LayerNorm ============
__global__ void pool_ln_kernel(const float* __restrict__ gamma, const float* __restrict__ beta,
                               const int* __restrict__ heads, const int* __restrict__ tails)
{
    __shared__ float red[32];
    const int span = blockIdx.x;
    const int tid = threadIdx.x;
    const int b = span >> 5;
    const int head = heads[span], tail = tails[span];

    float4 acc = make_float4(0.f, 0.f, 0.f, 0.f);
    for (int s = head + 1; s < tail; s++) {
        const float4 v = *(const float4*)(g_enc + ((size_t)b * SS + s) * HH + tid * 4);
        acc.x += v.x; acc.y += v.y; acc.z += v.z; acc.w += v.w;
    }
    const float invc = 1.f / (float)(tail - head - 1);
    acc.x *= invc; acc.y *= invc; acc.z *= invc; acc.w *= invc;

    const float mu = blk_sum256(acc.x + acc.y + acc.z + acc.w, red) * (1.f / HH);
    const float dx = acc.x - mu, dy = acc.y - mu, dz = acc.z - mu, dw = acc.w - mu;
    const float var = blk_sum256(dx*dx + dy*dy + dz*dz + dw*dw, red) * (1.f / HH);
    const float rstd = rsqrtf(var + 1e-7f);

    const int h = tid * 4;
    const float4 gm = *(const float4*)(gamma + h);
    const float4 bt = *(const float4*)(beta + h);
    float4 o = make_float4(dx*rstd*gm.x + bt.x, dy*rstd*gm.y + bt.y,
                           dz*rstd*gm.z + bt.z, dw*rstd*gm.w + bt.w);
    *(float4*)(g_pool + (size_t)span * HH + h) = o;
}

// ============ residual LayerNorm: g_attn = LN(g_wo + g_pool) ============
__global__ void ln_res_kernel(const float* __restrict__ gamma, const float* __restrict__ beta)
{
    __shared__ float red[32];
    const int row = blockIdx.x;
    const int tid = threadIdx.x;
    const size_t off = (size_t)row * HH + tid * 4;

    float4 x = *(const float4*)(g_wo + off);
    const float4 p = *(const float4*)(g_pool + off);
    x.x += p.x; x.y += p.y; x.z += p.z; x.w += p.w;

    const float mu = blk_sum256(x.x + x.y + x.z + x.w, red) * (1.f / HH);
    const float dx = x.x - mu, dy = x.y - mu, dz = x.z - mu, dw = x.w - mu;
    const float var = blk_sum256(dx*dx + dy*dy + dz*dz + dw*dw, red) * (1.f / HH);
    const float rstd = rsqrtf(var + 1e-7f);

    const int h = tid * 4;
    const float4 gm = *(const float4*)(gamma + h);
    const float4 bt = *(const float4*)(beta + h);
    float4 o = make_float4(dx*rstd*gm.x + bt.x, dy*rstd*gm.y + bt.y,
                           dz*rstd*gm.z + bt.z, dw*rstd*gm.w + bt.w);
    *(float4*)(g_attn + off) = o;
}

// ============ span attention: one CTA per (b, head) ============
__global__ void attn_kernel(const int* __restrict__ mask)
{
    __shared__ float Qs[32][65], Ks[32][65], Vs[32][65];
    __shared__ float P[32][33];
    __shared__ int ms[32];

    const int bh = blockIdx.x;
    const int b = bh / NHEADS, hd = bh % NHEADS;
    const int tid = threadIdx.x;
    const size_t rowbase = (size_t)b * NSPAN;
    const int col0 = hd * DHEAD;

    for (int i = tid; i < NSPAN * DHEAD; i += 128) {
        const int n = i >> 6, d = i & 63;
        const size_t off = (rowbase + n) * HH + col0 + d;
        Qs[n][d] = g_q[off];
        Ks[n][d] = g_k[off];
        Vs[n][d] = g_v[off];
    }
    if (tid < 32) ms[tid] = mask[b * NSPAN + tid];
    __syncthreads();

    for (int i = tid; i < 1024; i += 128) {
        const int qi = i >> 5, kj = i & 31;
        float s = 0.f;
#pragma unroll
        for (int d = 0; d < 64; d++) s += Qs[qi][d] * Ks[kj][d];
        s *= 0.125f;
        P[qi][kj] = (ms[qi] && ms[kj]) ? s : -3.402823466e38f;
    }
    __syncthreads();

    if (tid < 32) {
        float mx = -3.402823466e38f;
#pragma unroll
        for (int j = 0; j < 32; j++) mx = fmaxf(mx, P[tid][j]);
        float sum = 0.f;
#pragma unroll
        for (int j = 0; j < 32; j++) { float e = expf(P[tid][j] - mx); P[tid][j] = e; sum += e; }
        const float inv = 1.f / sum;
#pragma unroll
        for (int j = 0; j < 32; j++) P[tid][j] = (ms[tid] && ms[j]) ? P[tid][j] * inv : 0.f;
    }
    __syncthreads();

    for (int i = tid; i < NSPAN * DHEAD; i += 128) {
        const int qi = i >> 6, d = i & 63;
        float s = 0.f;
#pragma unroll
        for (int j = 0; j < 32; j++) s += P[qi][j] * Vs[j][d];
        g_ctx[(rowbase + qi) * HH + col0 + d] = s;
    }
}

// ============ launch ============
extern "C" void kernel_launch(void* const* d_in, const int* in_sizes, int n_in,
                              void* d_out, int out_size)
{
    const float* enc_in  = (const float*)d_in[0];
    const float* W_ih    = (const float*)d_in[1];
    const float* W_hh    = (const float*)d_in[2];
    const float* b_ih    = (const float*)d_in[3];
    const float* b_hh    = (const float*)d_in[4];
    const float* ln_g    = (const float*)d_in[5];
    const float* ln_b    = (const float*)d_in[6];
    const float* Wq      = (const float*)d_in[7];
    const float* bq      = (const float*)d_in[8];
    const float* Wk      = (const float*)d_in[9];
    const float* bk      = (const float*)d_in[10];
    const float* Wv      = (const float*)d_in[11];
    const float* bv      = (const float*)d_in[12];
    const float* Wo      = (const float*)d_in[13];
    const float* bo      = (const float*)d_in[14];
    const float* aln_g   = (const float*)d_in[15];
    const float* aln_b   = (const float*)d_in[16];
    const float* clf_W   = (const float*)d_in[17];
    const float* clf_b   = (const float*)d_in[18];
    const int*   heads   = (const int*)d_in[19];
    const int*   tails   = (const int*)d_in[20];
    const int*   mask    = (const int*)d_in[21];
    float* out = (float*)d_out;

    float *gates, *pool, *q, *k, *v, *ctx, *attn;
    cudaGetSymbolAddress((void**)&gates, g_gates);
    cudaGetSymbolAddress((void**)&pool,  g_pool);
    cudaGetSymbolAddress((void**)&q,     g_q);
    cudaGetSymbolAddress((void**)&k,     g_k);
    cudaGetSymbolAddress((void**)&v,     g_v);
    cudaGetSymbolAddress((void**)&ctx,   g_ctx);
    float* wo_buf;
    cudaGetSymbolAddress((void**)&wo_buf, g_wo);
    cudaGetSymbolAddress((void**)&attn,  g_attn);

    // 1. gates = X @ W_ih^T + b_ih + b_hh
    sgemm_nt<<<dim3(HX4 / 128, (BB * SS) / 128), 256>>>(
        enc_in, W_ih, b_ih, b_hh, gates, BB * SS, HX4, HH);

    // 2. persistent LSTM
    const int smem = (32 * WPAD + 16 * 1024 + 32 * 17 + 128) * sizeof(float);
    cudaFuncSetAttribute(lstm_kernel, cudaFuncAttributeMaxDynamicSharedMemorySize, smem);
    lstm_kernel<<<NCTA, 128, smem>>>(W_hh);

    // 3. span pool + LN
    pool_ln_kernel<<<BB * NSPAN, 256>>>(ln_g, ln_b, heads, tails);

    // 4. QKV projections
    sgemm_nt<<<dim3(HH / 128, (BB * NSPAN) / 128), 256>>>(pool, Wq, bq, nullptr, q, BB * NSPAN, HH, HH);
    sgemm_nt<<<dim3(HH / 128, (BB * NSPAN) / 128), 256>>>(pool, Wk, bk, nullptr, k, BB * NSPAN, HH, HH);
    sgemm_nt<<<dim3(HH / 128, (BB * NSPAN) / 128), 256>>>(pool, Wv, bv, nullptr, v, BB * NSPAN, HH, HH);

    // 5. attention
    attn_kernel<<<BB * NHEADS, 128>>>(mask);

    // 6. output projection
    sgemm_nt<<<dim3(HH / 128, (BB * NSPAN) / 128), 256>>>(ctx, Wo, bo, nullptr, wo_buf, BB * NSPAN, HH, HH);

    // 7. residual LN
    ln_res_kernel<<<BB * NSPAN, 256>>>(aln_g, aln_b);

    // 8. classifier -> d_out [B,NS,L]
    sgemm_nt<<<dim3(1, (BB * NSPAN) / 128), 256>>>(attn, clf_W, clf_b, nullptr, out, BB * NSPAN, NCLS, HH);
}

// round 4
// speedup vs baseline: 1.0856x; 1.0856x over previous
#include <cuda_runtime.h>
#include <math.h>
#include <stdint.h>

#define BB      16
#define SS      1024
#define HH      1024
#define HX4     4096
#define NSPAN   32
#define NHEADS  16
#define DHEAD   64
#define NCLS    5
#define NCTA    128
#define UPC     8
#define WPAD    1028

// ---------------- device scratch ----------------
__device__ float g_gates[(size_t)BB * SS * HX4];
__device__ float g_enc  [(size_t)BB * SS * HH];
__device__ float g_h    [2][HH * BB];          // [unit][batch] (k-major)
__device__ volatile int g_flags[NCTA];
__device__ float g_pool [BB * NSPAN * HH];
__device__ float g_q    [BB * NSPAN * HH];
__device__ float g_k    [BB * NSPAN * HH];
__device__ float g_v    [BB * NSPAN * HH];
__device__ float g_ctx  [BB * NSPAN * HH];
__device__ float g_wo   [BB * NSPAN * HH];
__device__ float g_attn [BB * NSPAN * HH];

// ---------------- small asm helpers ----------------
__device__ __forceinline__ uint32_t f2tf32(float x) {
    uint32_t r; asm("cvt.rna.tf32.f32 %0, %1;" : "=r"(r) : "f"(x)); return r;
}
__device__ __forceinline__ void mma_tf32(float* c, const uint32_t* a, const uint32_t* b) {
    asm volatile("mma.sync.aligned.m16n8k8.row.col.f32.tf32.tf32.f32 "
        "{%0,%1,%2,%3}, {%4,%5,%6,%7}, {%8,%9}, {%0,%1,%2,%3};"
        : "+f"(c[0]), "+f"(c[1]), "+f"(c[2]), "+f"(c[3])
        : "r"(a[0]), "r"(a[1]), "r"(a[2]), "r"(a[3]), "r"(b[0]), "r"(b[1]));
}
__device__ __forceinline__ unsigned long long fma2(unsigned long long a,
                                                   unsigned long long b,
                                                   unsigned long long c) {
    unsigned long long d;
    asm("fma.rn.f32x2 %0, %1, %2, %3;" : "=l"(d) : "l"(a), "l"(b), "l"(c));
    return d;
}
__device__ __forceinline__ unsigned long long splat2(float x) {
    unsigned long long d; asm("mov.b64 %0, {%1, %1};" : "=l"(d) : "f"(x)); return d;
}
__device__ __forceinline__ void unpack2(unsigned long long v, float& lo, float& hi) {
    asm("mov.b64 {%0, %1}, %2;" : "=f"(lo), "=f"(hi) : "l"(v));
}

// =====================================================================
// tf32 tensor-core GEMM: C[M,N] = A[M,K] @ W[N,K]^T + b1 (+ b2)
// grid (N/128, M/128), 256 threads. Requires M%128==0, N%128==0, K%16==0.
// =====================================================================
__global__ void __launch_bounds__(256)
mma_gemm_nt(const float* __restrict__ A, const float* __restrict__ W,
            const float* __restrict__ b1, const float* __restrict__ b2,
            float* __restrict__ C, int M, int N, int K)
{
    __shared__ uint32_t As[16][136];
    __shared__ uint32_t Ws[16][136];

    const int tid = threadIdx.x;
    const int lane = tid & 31, warp = tid >> 5;
    const int wm = (warp >> 2) * 64;      // warp m-offset within tile (0/64)
    const int wnn = (warp & 3) * 32;      // warp n-offset (0..96)
    const int tig = lane & 3, grp = lane >> 2;

    const int n0 = blockIdx.x * 128, m0 = blockIdx.y * 128;
    const int lr = tid >> 1;              // 0..127
    const int kq = (tid & 1) * 8;

    float c[4][4][4];
#pragma unroll
    for (int mi = 0; mi < 4; mi++)
#pragma unroll
        for (int ni = 0; ni < 4; ni++)
#pragma unroll
            for (int j = 0; j < 4; j++) c[mi][ni][j] = 0.f;

    const float* Ap = A + (size_t)(m0 + lr) * K + kq;
    const float* Wp = W + (size_t)(n0 + lr) * K + kq;

    for (int k0 = 0; k0 < K; k0 += 16) {
        const float4 av0 = *(const float4*)(Ap + k0);
        const float4 av1 = *(const float4*)(Ap + k0 + 4);
        const float4 wv0 = *(const float4*)(Wp + k0);
        const float4 wv1 = *(const float4*)(Wp + k0 + 4);
        As[kq+0][lr] = f2tf32(av0.x); As[kq+1][lr] = f2tf32(av0.y);
        As[kq+2][lr] = f2tf32(av0.z); As[kq+3][lr] = f2tf32(av0.w);
        As[kq+4][lr] = f2tf32(av1.x); As[kq+5][lr] = f2tf32(av1.y);
        As[kq+6][lr] = f2tf32(av1.z); As[kq+7][lr] = f2tf32(av1.w);
        Ws[kq+0][lr] = f2tf32(wv0.x); Ws[kq+1][lr] = f2tf32(wv0.y);
        Ws[kq+2][lr] = f2tf32(wv0.z); Ws[kq+3][lr] = f2tf32(wv0.w);
        Ws[kq+4][lr] = f2tf32(wv1.x); Ws[kq+5][lr] = f2tf32(wv1.y);
        Ws[kq+6][lr] = f2tf32(wv1.z); Ws[kq+7][lr] = f2tf32(wv1.w);
        __syncthreads();

#pragma unroll
        for (int ks = 0; ks < 16; ks += 8) {
            uint32_t a[4][4], b[4][2];
#pragma unroll
            for (int mi = 0; mi < 4; mi++) {
                const int rb = wm + mi * 16 + grp;
                a[mi][0] = As[ks + tig][rb];
                a[mi][1] = As[ks + tig][rb + 8];
                a[mi][2] = As[ks + tig + 4][rb];
                a[mi][3] = As[ks + tig + 4][rb + 8];
            }
#pragma unroll
            for (int ni = 0; ni < 4; ni++) {
                const int nb = wnn + ni * 8 + grp;
                b[ni][0] = Ws[ks + tig][nb];
                b[ni][1] = Ws[ks + tig + 4][nb];
            }
#pragma unroll
            for (int mi = 0; mi < 4; mi++)
#pragma unroll
                for (int ni = 0; ni < 4; ni++)
                    mma_tf32(c[mi][ni], a[mi], b[ni]);
        }
        __syncthreads();
    }

#pragma unroll
    for (int ni = 0; ni < 4; ni++) {
        const int col = n0 + wnn + ni * 8 + tig * 2;
        float bias0 = b1[col], bias1 = b1[col + 1];
        if (b2) { bias0 += b2[col]; bias1 += b2[col + 1]; }
#pragma unroll
        for (int mi = 0; mi < 4; mi++) {
            const int row = m0 + wm + mi * 16 + grp;
            C[(size_t)row * N + col]           = c[mi][ni][0] + bias0;
            C[(size_t)row * N + col + 1]       = c[mi][ni][1] + bias1;
            C[(size_t)(row + 8) * N + col]     = c[mi][ni][2] + bias0;
            C[(size_t)(row + 8) * N + col + 1] = c[mi][ni][3] + bias1;
        }
    }
}

// ============ fp32 GEMM for the tiny classifier (N=5) ============
__global__ void sgemm_nt(const float* __restrict__ A, const float* __restrict__ W,
                         const float* __restrict__ b1,
                         float* __restrict__ C, int M, int N, int K)
{
    __shared__ float As[8][128];
    __shared__ float Ws[8][132];
    const int tid = threadIdx.x;
    const int n0 = blockIdx.x * 128, m0 = blockIdx.y * 128;
    const int lr = tid >> 1, lk = (tid & 1) << 2;
    const int tx = tid & 15, ty = tid >> 4;

    float acc[8][8];
#pragma unroll
    for (int i = 0; i < 8; i++)
#pragma unroll
        for (int j = 0; j < 8; j++) acc[i][j] = 0.f;

    const float* Arow = A + (size_t)(m0 + lr) * K + lk;
    const int wn = n0 + lr;
    const bool wok = (wn < N);
    const float* Wrow = W + (size_t)(wok ? wn : 0) * K + lk;

    for (int k0 = 0; k0 < K; k0 += 8) {
        float4 av = *(const float4*)(Arow + k0);
        float4 wv = make_float4(0.f, 0.f, 0.f, 0.f);
        if (wok) wv = *(const float4*)(Wrow + k0);
        As[lk + 0][lr] = av.x; As[lk + 1][lr] = av.y;
        As[lk + 2][lr] = av.z; As[lk + 3][lr] = av.w;
        Ws[lk + 0][lr] = wv.x; Ws[lk + 1][lr] = wv.y;
        Ws[lk + 2][lr] = wv.z; Ws[lk + 3][lr] = wv.w;
        __syncthreads();
#pragma unroll
        for (int kk = 0; kk < 8; kk++) {
            float a[8], w[8];
#pragma unroll
            for (int i = 0; i < 8; i++) a[i] = As[kk][ty * 8 + i];
#pragma unroll
            for (int j = 0; j < 8; j++) w[j] = Ws[kk][tx * 8 + j];
#pragma unroll
            for (int i = 0; i < 8; i++)
#pragma unroll
                for (int j = 0; j < 8; j++) acc[i][j] += a[i] * w[j];
        }
        __syncthreads();
    }
#pragma unroll
    for (int i = 0; i < 8; i++) {
        const int m = m0 + ty * 8 + i;
#pragma unroll
        for (int j = 0; j < 8; j++) {
            const int n = n0 + tx * 8 + j;
            if (n < N) C[(size_t)m * N + n] = acc[i][j] + b1[n];
        }
    }
}

// ============ persistent LSTM: 128 CTAs x 128 threads, f32x2 path ============
__global__ void __launch_bounds__(128, 1)
lstm_kernel(const float* __restrict__ Whh)
{
    extern __shared__ float sm[];
    float* Wsh  = sm;                       // [32][WPAD]
    float* hsh  = Wsh + 32 * WPAD;          // [1024][16] (k-major)
    float* gbuf = hsh + HH * BB;            // [32][17]
    float* cst  = gbuf + 32 * 17;           // [128]

    const int tid = threadIdx.x;
    const int cta = blockIdx.x;

    for (int i = tid; i < 32 * 256; i += 128) {
        const int rr = i >> 8, c4 = (i & 255) << 2;
        const int gg = rr >> 3, uu = rr & 7;
        const int j = gg * 1024 + cta * UPC + uu;
        *(float4*)(Wsh + rr * WPAD + c4) = *(const float4*)(Whh + (size_t)j * HH + c4);
    }
    cst[tid] = 0.f;
    const int base = g_flags[cta];
    __syncthreads();

    const int r  = tid & 31;
    const int bq = tid >> 5;                 // batch quad 0..3
    const float4* wrow4 = (const float4*)(Wsh + r * WPAD);
    const int gg = r >> 3, uu = r & 7;
    const int jrow = gg * 1024 + cta * UPC + uu;
    const int su = tid & 7, sb = tid >> 3;
    const int unit = cta * UPC + su;

    for (int t = 0; t < SS; t++) {
        // prefetch input-gate contributions (independent of barrier)
        const size_t gb = (size_t)t * HX4 + jrow;
        const float gt0 = __ldcg(g_gates + (size_t)(bq * 4 + 0) * SS * HX4 + gb);
        const float gt1 = __ldcg(g_gates + (size_t)(bq * 4 + 1) * SS * HX4 + gb);
        const float gt2 = __ldcg(g_gates + (size_t)(bq * 4 + 2) * SS * HX4 + gb);
        const float gt3 = __ldcg(g_gates + (size_t)(bq * 4 + 3) * SS * HX4 + gb);

        unsigned long long acc01 = 0ull, acc23 = 0ull;
        if (t > 0) {
            if (tid < 32) {
                const int tgt = base + t;
                for (;;) {
                    bool ok = (g_flags[tid] >= tgt) && (g_flags[tid + 32] >= tgt) &&
                              (g_flags[tid + 64] >= tgt) && (g_flags[tid + 96] >= tgt);
                    if (__all_sync(0xffffffffu, ok)) break;
                    __nanosleep(64);
                }
            }
            __syncthreads();
            __threadfence();
            const float* hsrc = g_h[t & 1];
            for (int i = tid; i < (HH * BB) / 4; i += 128)
                *(float4*)(hsh + i * 4) = __ldcg((const float4*)(hsrc) + i);
            __syncthreads();

            const char* hbase = (const char*)(hsh + bq * 4);
#pragma unroll 2
            for (int k4 = 0; k4 < 256; k4++) {
                const float4 w = wrow4[k4];
                const ulonglong2 h0 = *(const ulonglong2*)(hbase + ((k4 * 4 + 0) << 6));
                const ulonglong2 h1 = *(const ulonglong2*)(hbase + ((k4 * 4 + 1) << 6));
                const ulonglong2 h2 = *(const ulonglong2*)(hbase + ((k4 * 4 + 2) << 6));
                const ulonglong2 h3 = *(const ulonglong2*)(hbase + ((k4 * 4 + 3) << 6));
                unsigned long long w2;
                w2 = splat2(w.x); acc01 = fma2(w2, h0.x, acc01); acc23 = fma2(w2, h0.y, acc23);
                w2 = splat2(w.y); acc01 = fma2(w2, h1.x, acc01); acc23 = fma2(w2, h1.y, acc23);
                w2 = splat2(w.z); acc01 = fma2(w2, h2.x, acc01); acc23 = fma2(w2, h2.y, acc23);
                w2 = splat2(w.w); acc01 = fma2(w2, h3.x, acc01); acc23 = fma2(w2, h3.y, acc23);
            }
        }
        float a0, a1, a2, a3;
        unpack2(acc01, a0, a1);
        unpack2(acc23, a2, a3);
        gbuf[r * 17 + (bq * 4 + 0)] = a0 + gt0;
        gbuf[r * 17 + (bq * 4 + 1)] = a1 + gt1;
        gbuf[r * 17 + (bq * 4 + 2)] = a2 + gt2;
        gbuf[r * 17 + (bq * 4 + 3)] = a3 + gt3;
        __syncthreads();
        {
            const float iv = gbuf[(0 * 8 + su) * 17 + sb];
            const float fv = gbuf[(1 * 8 + su) * 17 + sb];
            const float gv = gbuf[(2 * 8 + su) * 17 + sb];
            const float ov = gbuf[(3 * 8 + su) * 17 + sb];
            const float ig = 1.f / (1.f + expf(-iv));
            const float fg = 1.f / (1.f + expf(-fv));
            const float og = 1.f / (1.f + expf(-ov));
            const float c = fg * cst[tid] + ig * tanhf(gv);
            cst[tid] = c;
            const float h = og * tanhf(c);
            g_h[(t + 1) & 1][unit * BB + sb] = h;
            g_enc[((size_t)sb * SS + t) * HH + unit] = h;
        }
        __threadfence();
        __syncthreads();
        if (tid == 0) g_flags[cta] = base + t + 1;
    }
}

// ============ block reduction helper (256 threads) ============
__device__ __forceinline__ float blk_sum256(float v, float* red)
{
#pragma unroll
    for (int o = 16; o > 0; o >>= 1) v += __shfl_down_sync(0xffffffffu, v, o);
    const int tid = threadIdx.x;
    if ((tid & 31) == 0) red[tid >> 5] = v;
    __syncthreads();
    if (tid < 32) {
        float x = (tid < 8) ? red[tid] : 0.f;
#pragma unroll
        for (int o = 4; o > 0; o >>= 1) x += __shfl_down_sync(0xffffffffu, x, o);
        if (tid == 0) red[0] = x;
    }
    __syncthreads();
    const float s = red[0];
    __syncthreads();
    return s;
}

// ============ span mean-pool + LayerNorm ============
__global__ void pool_ln_kernel(const float* __restrict__ gamma, const float* __restrict__ beta,
                               const int* __restrict__ heads, const int* __restrict__ tails)
{
    __shared__ float red[32];
    const int span = blockIdx.x;
    const int tid = threadIdx.x;
    const int b = span >> 5;
    const int head = heads[span], tail = tails[span];

    float4 acc = make_float4(0.f, 0.f, 0.f, 0.f);
    for (int s = head + 1; s < tail; s++) {
        const float4 v = *(const float4*)(g_enc + ((size_t)b * SS + s) * HH + tid * 4);
        acc.x += v.x; acc.y += v.y; acc.z += v.z; acc.w += v.w;
    }
    const float invc = 1.f / (float)(tail - head - 1);
    acc.x *= invc; acc.y *= invc; acc.z *= invc; acc.w *= invc;

    const float mu = blk_sum256(acc.x + acc.y + acc.z + acc.w, red) * (1.f / HH);
    const float dx = acc.x - mu, dy = acc.y - mu, dz = acc.z - mu, dw = acc.w - mu;
    const float var = blk_sum256(dx*dx + dy*dy + dz*dz + dw*dw, red) * (1.f / HH);
    const float rstd = rsqrtf(var + 1e-7f);

    const int h = tid * 4;
    const float4 gm = *(const float4*)(gamma + h);
    const float4 bt = *(const float4*)(beta + h);
    float4 o = make_float4(dx*rstd*gm.x + bt.x, dy*rstd*gm.y + bt.y,
                           dz*rstd*gm.z + bt.z, dw*rstd*gm.w + bt.w);
    *(float4*)(g_pool + (size_t)span * HH + h) = o;
}

// ============ residual LayerNorm ============
__global__ void ln_res_kernel(const float* __restrict__ gamma, const float* __restrict__ beta)
{
    __shared__ float red[32];
    const int row = blockIdx.x;
    const int tid = threadIdx.x;
    const size_t off = (size_t)row * HH + tid * 4;

    float4 x = *(const float4*)(g_wo + off);
    const float4 p = *(const float4*)(g_pool + off);
    x.x += p.x; x.y += p.y; x.z += p.z; x.w += p.w;

    const float mu = blk_sum256(x.x + x.y + x.z + x.w, red) * (1.f / HH);
    const float dx = x.x - mu, dy = x.y - mu, dz = x.z - mu, dw = x.w - mu;
    const float var = blk_sum256(dx*dx + dy*dy + dz*dz + dw*dw, red) * (1.f / HH);
    const float rstd = rsqrtf(var + 1e-7f);

    const int h = tid * 4;
    const float4 gm = *(const float4*)(gamma + h);
    const float4 bt = *(const float4*)(beta + h);
    float4 o = make_float4(dx*rstd*gm.x + bt.x, dy*rstd*gm.y + bt.y,
                           dz*rstd*gm.z + bt.z, dw*rstd*gm.w + bt.w);
    *(float4*)(g_attn + off) = o;
}

// ============ span attention: one CTA per (b, head) ============
__global__ void attn_kernel(const int* __restrict__ mask)
{
    __shared__ float Qs[32][65], Ks[32][65], Vs[32][65];
    __shared__ float P[32][33];
    __shared__ int ms[32];

    const int bh = blockIdx.x;
    const int b = bh / NHEADS, hd = bh % NHEADS;
    const int tid = threadIdx.x;
    const size_t rowbase = (size_t)b * NSPAN;
    const int col0 = hd * DHEAD;

    for (int i = tid; i < NSPAN * DHEAD; i += 128) {
        const int n = i >> 6, d = i & 63;
        const size_t off = (rowbase + n) * HH + col0 + d;
        Qs[n][d] = g_q[off];
        Ks[n][d] = g_k[off];
        Vs[n][d] = g_v[off];
    }
    if (tid < 32) ms[tid] = mask[b * NSPAN + tid];
    __syncthreads();

    for (int i = tid; i < 1024; i += 128) {
        const int qi = i >> 5, kj = i & 31;
        float s = 0.f;
#pragma unroll
        for (int d = 0; d < 64; d++) s += Qs[qi][d] * Ks[kj][d];
        s *= 0.125f;
        P[qi][kj] = (ms[qi] && ms[kj]) ? s : -3.402823466e38f;
    }
    __syncthreads();

    if (tid < 32) {
        float mx = -3.402823466e38f;
#pragma unroll
        for (int j = 0; j < 32; j++) mx = fmaxf(mx, P[tid][j]);
        float sum = 0.f;
#pragma unroll
        for (int j = 0; j < 32; j++) { float e = expf(P[tid][j] - mx); P[tid][j] = e; sum += e; }
        const float inv = 1.f / sum;
#pragma unroll
        for (int j = 0; j < 32; j++) P[tid][j] = (ms[tid] && ms[j]) ? P[tid][j] * inv : 0.f;
    }
    __syncthreads();

    for (int i = tid; i < NSPAN * DHEAD; i += 128) {
        const int qi = i >> 6, d = i & 63;
        float s = 0.f;
#pragma unroll
        for (int j = 0; j < 32; j++) s += P[qi][j] * Vs[j][d];
        g_ctx[(rowbase + qi) * HH + col0 + d] = s;
    }
}

// ============ launch ============
extern "C" void kernel_launch(void* const* d_in, const int* in_sizes, int n_in,
                              void* d_out, int out_size)
{
    const float* enc_in  = (const float*)d_in[0];
    const float* W_ih    = (const float*)d_in[1];
    const float* W_hh    = (const float*)d_in[2];
    const float* b_ih    = (const float*)d_in[3];
    const float* b_hh    = (const float*)d_in[4];
    const float* ln_g    = (const float*)d_in[5];
    const float* ln_b    = (const float*)d_in[6];
    const float* Wq      = (const float*)d_in[7];
    const float* bq      = (const float*)d_in[8];
    const float* Wk      = (const float*)d_in[9];
    const float* bk      = (const float*)d_in[10];
    const float* Wv      = (const float*)d_in[11];
    const float* bv      = (const float*)d_in[12];
    const float* Wo      = (const float*)d_in[13];
    const float* bo      = (const float*)d_in[14];
    const float* aln_g   = (const float*)d_in[15];
    const float* aln_b   = (const float*)d_in[16];
    const float* clf_W   = (const float*)d_in[17];
    const float* clf_b   = (const float*)d_in[18];
    const int*   heads   = (const int*)d_in[19];
    const int*   tails   = (const int*)d_in[20];
    const int*   mask    = (const int*)d_in[21];
    float* out = (float*)d_out;

    float *gates, *pool, *q, *k, *v, *ctx, *wo_buf, *attn;
    cudaGetSymbolAddress((void**)&gates,  g_gates);
    cudaGetSymbolAddress((void**)&pool,   g_pool);
    cudaGetSymbolAddress((void**)&q,      g_q);
    cudaGetSymbolAddress((void**)&k,      g_k);
    cudaGetSymbolAddress((void**)&v,      g_v);
    cudaGetSymbolAddress((void**)&ctx,    g_ctx);
    cudaGetSymbolAddress((void**)&wo_buf, g_wo);
    cudaGetSymbolAddress((void**)&attn,   g_attn);

    // 1. gates = X @ W_ih^T + b_ih + b_hh   (tf32 tensor cores)
    mma_gemm_nt<<<dim3(HX4 / 128, (BB * SS) / 128), 256>>>(
        enc_in, W_ih, b_ih, b_hh, gates, BB * SS, HX4, HH);

    // 2. persistent LSTM (fp32, f32x2 packed FMA)
    const int smem = (32 * WPAD + HH * BB + 32 * 17 + 128) * sizeof(float);
    cudaFuncSetAttribute(lstm_kernel, cudaFuncAttributeMaxDynamicSharedMemorySize, smem);
    lstm_kernel<<<NCTA, 128, smem>>>(W_hh);

    // 3. span pool + LN
    pool_ln_kernel<<<BB * NSPAN, 256>>>(ln_g, ln_b, heads, tails);

    // 4. QKV projections (tf32)
    mma_gemm_nt<<<dim3(HH / 128, (BB * NSPAN) / 128), 256>>>(pool, Wq, bq, nullptr, q, BB * NSPAN, HH, HH);
    mma_gemm_nt<<<dim3(HH / 128, (BB * NSPAN) / 128), 256>>>(pool, Wk, bk, nullptr, k, BB * NSPAN, HH, HH);
    mma_gemm_nt<<<dim3(HH / 128, (BB * NSPAN) / 128), 256>>>(pool, Wv, bv, nullptr, v, BB * NSPAN, HH, HH);

    // 5. attention
    attn_kernel<<<BB * NHEADS, 128>>>(mask);

    // 6. output projection (tf32)
    mma_gemm_nt<<<dim3(HH / 128, (BB * NSPAN) / 128), 256>>>(ctx, Wo, bo, nullptr, wo_buf, BB * NSPAN, HH, HH);

    // 7. residual LN
    ln_res_kernel<<<BB * NSPAN, 256>>>(aln_g, aln_b);

    // 8. classifier -> d_out [B,NS,L]
    sgemm_nt<<<dim3(1, (BB * NSPAN) / 128), 256>>>(attn, clf_W, clf_b, out, BB * NSPAN, NCLS, HH);
}

// round 5
// speedup vs baseline: 1.7453x; 1.6076x over previous
#include <cuda_runtime.h>
#include <cuda_bf16.h>
#include <math.h>
#include <stdint.h>

#define BB      16
#define SS      1024
#define HH      1024
#define HX4     4096
#define NSPAN   32
#define NHEADS  16
#define DHEAD   64
#define NCLS    5
#define NCTA    128
#define UPC     8
#define WSTRIDE 1032   // padded bf16 row stride (1032*2B=2064B; 516 words % 32 = 4 -> conflict-free ldmatrix)

// ---------------- device scratch ----------------
__device__ float g_gates[(size_t)BB * SS * HX4];
__device__ float g_enc  [(size_t)BB * SS * HH];
__device__ __nv_bfloat16 g_hhi[2][BB * HH];    // [b][unit] hidden state, bf16 hi part
__device__ __nv_bfloat16 g_hlo[2][BB * HH];    // bf16 lo (residual) part
__device__ volatile int g_flags[NCTA];
__device__ float g_pool [BB * NSPAN * HH];
__device__ float g_q    [BB * NSPAN * HH];
__device__ float g_k    [BB * NSPAN * HH];
__device__ float g_v    [BB * NSPAN * HH];
__device__ float g_ctx  [BB * NSPAN * HH];
__device__ float g_wo   [BB * NSPAN * HH];
__device__ float g_attn [BB * NSPAN * HH];

// ---------------- asm helpers ----------------
__device__ __forceinline__ uint32_t f2tf32(float x) {
    uint32_t r; asm("cvt.rna.tf32.f32 %0, %1;" : "=r"(r) : "f"(x)); return r;
}
__device__ __forceinline__ void mma_tf32(float* c, const uint32_t* a, const uint32_t* b) {
    asm volatile("mma.sync.aligned.m16n8k8.row.col.f32.tf32.tf32.f32 "
        "{%0,%1,%2,%3}, {%4,%5,%6,%7}, {%8,%9}, {%0,%1,%2,%3};"
        : "+f"(c[0]), "+f"(c[1]), "+f"(c[2]), "+f"(c[3])
        : "r"(a[0]), "r"(a[1]), "r"(a[2]), "r"(a[3]), "r"(b[0]), "r"(b[1]));
}
__device__ __forceinline__ void mma_bf16(float* c, const uint32_t* a, const uint32_t* b) {
    asm volatile("mma.sync.aligned.m16n8k16.row.col.f32.bf16.bf16.f32 "
        "{%0,%1,%2,%3}, {%4,%5,%6,%7}, {%8,%9}, {%0,%1,%2,%3};"
        : "+f"(c[0]), "+f"(c[1]), "+f"(c[2]), "+f"(c[3])
        : "r"(a[0]), "r"(a[1]), "r"(a[2]), "r"(a[3]), "r"(b[0]), "r"(b[1]));
}
__device__ __forceinline__ void ldsm_x4(uint32_t* r, uint32_t addr) {
    asm volatile("ldmatrix.sync.aligned.m8n8.x4.shared.b16 {%0,%1,%2,%3}, [%4];"
        : "=r"(r[0]), "=r"(r[1]), "=r"(r[2]), "=r"(r[3]) : "r"(addr));
}
__device__ __forceinline__ void ldsm_x2(uint32_t* r, uint32_t addr) {
    asm volatile("ldmatrix.sync.aligned.m8n8.x2.shared.b16 {%0,%1}, [%2];"
        : "=r"(r[0]), "=r"(r[1]) : "r"(addr));
}
__device__ __forceinline__ uint32_t smem_u32(const void* p) {
    uint32_t a;
    asm("{ .reg .u64 t; cvta.to.shared.u64 t, %1; cvt.u32.u64 %0, t; }" : "=r"(a) : "l"(p));
    return a;
}
__device__ __forceinline__ void bsplit(float w, __nv_bfloat16& hi, __nv_bfloat16& lo) {
    hi = __float2bfloat16(w);
    lo = __float2bfloat16(w - __bfloat162float(hi));
}

// =====================================================================
// tf32 tensor-core GEMM: C[M,N] = A[M,K] @ W[N,K]^T + b1 (+ b2)
// =====================================================================
__global__ void __launch_bounds__(256)
mma_gemm_nt(const float* __restrict__ A, const float* __restrict__ W,
            const float* __restrict__ b1, const float* __restrict__ b2,
            float* __restrict__ C, int M, int N, int K)
{
    __shared__ uint32_t As[16][136];
    __shared__ uint32_t Ws[16][136];

    const int tid = threadIdx.x;
    const int lane = tid & 31, warp = tid >> 5;
    const int wm = (warp >> 2) * 64;
    const int wnn = (warp & 3) * 32;
    const int tig = lane & 3, grp = lane >> 2;

    const int n0 = blockIdx.x * 128, m0 = blockIdx.y * 128;
    const int lr = tid >> 1;
    const int kq = (tid & 1) * 8;

    float c[4][4][4];
#pragma unroll
    for (int mi = 0; mi < 4; mi++)
#pragma unroll
        for (int ni = 0; ni < 4; ni++)
#pragma unroll
            for (int j = 0; j < 4; j++) c[mi][ni][j] = 0.f;

    const float* Ap = A + (size_t)(m0 + lr) * K + kq;
    const float* Wp = W + (size_t)(n0 + lr) * K + kq;

    for (int k0 = 0; k0 < K; k0 += 16) {
        const float4 av0 = *(const float4*)(Ap + k0);
        const float4 av1 = *(const float4*)(Ap + k0 + 4);
        const float4 wv0 = *(const float4*)(Wp + k0);
        const float4 wv1 = *(const float4*)(Wp + k0 + 4);
        As[kq+0][lr] = f2tf32(av0.x); As[kq+1][lr] = f2tf32(av0.y);
        As[kq+2][lr] = f2tf32(av0.z); As[kq+3][lr] = f2tf32(av0.w);
        As[kq+4][lr] = f2tf32(av1.x); As[kq+5][lr] = f2tf32(av1.y);
        As[kq+6][lr] = f2tf32(av1.z); As[kq+7][lr] = f2tf32(av1.w);
        Ws[kq+0][lr] = f2tf32(wv0.x); Ws[kq+1][lr] = f2tf32(wv0.y);
        Ws[kq+2][lr] = f2tf32(wv0.z); Ws[kq+3][lr] = f2tf32(wv0.w);
        Ws[kq+4][lr] = f2tf32(wv1.x); Ws[kq+5][lr] = f2tf32(wv1.y);
        Ws[kq+6][lr] = f2tf32(wv1.z); Ws[kq+7][lr] = f2tf32(wv1.w);
        __syncthreads();

#pragma unroll
        for (int ks = 0; ks < 16; ks += 8) {
            uint32_t a[4][4], b[4][2];
#pragma unroll
            for (int mi = 0; mi < 4; mi++) {
                const int rb = wm + mi * 16 + grp;
                a[mi][0] = As[ks + tig][rb];
                a[mi][1] = As[ks + tig][rb + 8];
                a[mi][2] = As[ks + tig + 4][rb];
                a[mi][3] = As[ks + tig + 4][rb + 8];
            }
#pragma unroll
            for (int ni = 0; ni < 4; ni++) {
                const int nb = wnn + ni * 8 + grp;
                b[ni][0] = Ws[ks + tig][nb];
                b[ni][1] = Ws[ks + tig + 4][nb];
            }
#pragma unroll
            for (int mi = 0; mi < 4; mi++)
#pragma unroll
                for (int ni = 0; ni < 4; ni++)
                    mma_tf32(c[mi][ni], a[mi], b[ni]);
        }
        __syncthreads();
    }

#pragma unroll
    for (int ni = 0; ni < 4; ni++) {
        const int col = n0 + wnn + ni * 8 + tig * 2;
        float bias0 = b1[col], bias1 = b1[col + 1];
        if (b2) { bias0 += b2[col]; bias1 += b2[col + 1]; }
#pragma unroll
        for (int mi = 0; mi < 4; mi++) {
            const int row = m0 + wm + mi * 16 + grp;
            C[(size_t)row * N + col]           = c[mi][ni][0] + bias0;
            C[(size_t)row * N + col + 1]       = c[mi][ni][1] + bias1;
            C[(size_t)(row + 8) * N + col]     = c[mi][ni][2] + bias0;
            C[(size_t)(row + 8) * N + col + 1] = c[mi][ni][3] + bias1;
        }
    }
}

// ============ fp32 GEMM for the tiny classifier (N=5) ============
__global__ void sgemm_nt(const float* __restrict__ A, const float* __restrict__ W,
                         const float* __restrict__ b1,
                         float* __restrict__ C, int M, int N, int K)
{
    __shared__ float As[8][128];
    __shared__ float Ws[8][132];
    const int tid = threadIdx.x;
    const int n0 = blockIdx.x * 128, m0 = blockIdx.y * 128;
    const int lr = tid >> 1, lk = (tid & 1) << 2;
    const int tx = tid & 15, ty = tid >> 4;

    float acc[8][8];
#pragma unroll
    for (int i = 0; i < 8; i++)
#pragma unroll
        for (int j = 0; j < 8; j++) acc[i][j] = 0.f;

    const float* Arow = A + (size_t)(m0 + lr) * K + lk;
    const int wn = n0 + lr;
    const bool wok = (wn < N);
    const float* Wrow = W + (size_t)(wok ? wn : 0) * K + lk;

    for (int k0 = 0; k0 < K; k0 += 8) {
        float4 av = *(const float4*)(Arow + k0);
        float4 wv = make_float4(0.f, 0.f, 0.f, 0.f);
        if (wok) wv = *(const float4*)(Wrow + k0);
        As[lk + 0][lr] = av.x; As[lk + 1][lr] = av.y;
        As[lk + 2][lr] = av.z; As[lk + 3][lr] = av.w;
        Ws[lk + 0][lr] = wv.x; Ws[lk + 1][lr] = wv.y;
        Ws[lk + 2][lr] = wv.z; Ws[lk + 3][lr] = wv.w;
        __syncthreads();
#pragma unroll
        for (int kk = 0; kk < 8; kk++) {
            float a[8], w[8];
#pragma unroll
            for (int i = 0; i < 8; i++) a[i] = As[kk][ty * 8 + i];
#pragma unroll
            for (int j = 0; j < 8; j++) w[j] = Ws[kk][tx * 8 + j];
#pragma unroll
            for (int i = 0; i < 8; i++)
#pragma unroll
                for (int j = 0; j < 8; j++) acc[i][j] += a[i] * w[j];
        }
        __syncthreads();
    }
#pragma unroll
    for (int i = 0; i < 8; i++) {
        const int m = m0 + ty * 8 + i;
#pragma unroll
        for (int j = 0; j < 8; j++) {
            const int n = n0 + tx * 8 + j;
            if (n < N) C[(size_t)m * N + n] = acc[i][j] + b1[n];
        }
    }
}

// =====================================================================
// Persistent LSTM, tensor-core recurrent GEMM (split-bf16, 3x mma).
// 128 CTAs x 128 threads. CTA owns 32 gate rows (4 gates x 8 units).
// Warp w = gate w, 8 unit-columns; D[16 batch x 8 rows] in 4 fp32 regs.
// SMEM: W_hi/W_lo bf16 [32][WSTRIDE], h_hi/h_lo bf16 [16][WSTRIDE].
// =====================================================================
__global__ void __launch_bounds__(128, 1)
lstm_kernel(const float* __restrict__ Whh)
{
    extern __shared__ char smraw[];
    __nv_bfloat16* Whi = (__nv_bfloat16*)smraw;                    // 32*WSTRIDE
    __nv_bfloat16* Wlo = Whi + 32 * WSTRIDE;
    __nv_bfloat16* hhi = Wlo + 32 * WSTRIDE;                       // 16*WSTRIDE
    __nv_bfloat16* hlo = hhi + 16 * WSTRIDE;
    float* gbuf = (float*)(hlo + 16 * WSTRIDE);                    // [32][17]
    float* cst  = gbuf + 32 * 17;                                  // [128]

    const int tid = threadIdx.x;
    const int cta = blockIdx.x;
    const int lane = tid & 31, warp = tid >> 5;
    const int grp = lane >> 2, tig = lane & 3;

    // ---- one-time: split W_hh slice into bf16 hi/lo in SMEM ----
    for (int i = tid; i < 32 * 1024; i += 128) {
        const int r = i >> 10, k = i & 1023;
        const int jrow = (r >> 3) * 1024 + cta * UPC + (r & 7);
        __nv_bfloat16 hi, lo;
        bsplit(Whh[(size_t)jrow * HH + k], hi, lo);
        Whi[r * WSTRIDE + k] = hi;
        Wlo[r * WSTRIDE + k] = lo;
    }
    cst[tid] = 0.f;
    const int base = g_flags[cta];
    __syncthreads();

    // ldmatrix lane addresses
    const uint32_t a_row = lane & 15;
    const uint32_t a_colB = (lane >> 4) * 16;                       // 8 bf16 = 16 B
    const uint32_t ahi0 = smem_u32(hhi) + a_row * (WSTRIDE * 2) + a_colB;
    const uint32_t alo0 = smem_u32(hlo) + a_row * (WSTRIDE * 2) + a_colB;
    const uint32_t b_row = warp * 8 + (lane & 7);
    const uint32_t b_colB = ((lane >> 3) & 1) * 16;
    const uint32_t bhi0 = smem_u32(Whi) + b_row * (WSTRIDE * 2) + b_colB;
    const uint32_t blo0 = smem_u32(Wlo) + b_row * (WSTRIDE * 2) + b_colB;

    // gate-input addressing: lane covers rows r0,r0+1 and batches grp, grp+8
    const int r0 = warp * 8 + tig * 2;
    const int jrow0 = warp * 1024 + cta * UPC + tig * 2;            // consecutive pair
    const int su = tid & 7, sb = tid >> 3;
    const int unit = cta * UPC + su;

    for (int t = 0; t < SS; t++) {
        // prefetch input-gate contributions (barrier-independent)
        const float2 gt0 = *(const float2*)(g_gates + ((size_t)grp       * SS + t) * HX4 + jrow0);
        const float2 gt1 = *(const float2*)(g_gates + ((size_t)(grp + 8) * SS + t) * HX4 + jrow0);

        float c[4] = {0.f, 0.f, 0.f, 0.f};
        if (t > 0) {
            // grid barrier: wait for all CTAs to publish step t-1
            if (tid < 32) {
                const int tgt = base + t;
                for (;;) {
                    bool ok = (g_flags[tid] >= tgt) && (g_flags[tid + 32] >= tgt) &&
                              (g_flags[tid + 64] >= tgt) && (g_flags[tid + 96] >= tgt);
                    if (__all_sync(0xffffffffu, ok)) break;
                    __nanosleep(64);
                }
            }
            __syncthreads();
            __threadfence();

            // stage h_{t-1} (bf16 hi/lo) into SMEM
            const uint4* shi = (const uint4*)(g_hhi[t & 1]);
            const uint4* slo = (const uint4*)(g_hlo[t & 1]);
            for (int i = tid; i < 2048; i += 128) {
                const int b = i >> 7, cc = i & 127;                 // 8 bf16 per chunk
                *(uint4*)(hhi + b * WSTRIDE + cc * 8) = __ldcg(shi + i);
                *(uint4*)(hlo + b * WSTRIDE + cc * 8) = __ldcg(slo + i);
            }
            __syncthreads();

            // 64 k-tiles x (hi*hi + lo_h*hi_w + hi_h*lo_w)
#pragma unroll 4
            for (int kt = 0; kt < 64; kt++) {
                const uint32_t off = kt * 32;                       // 16 bf16 = 32 B
                uint32_t ah[4], al[4], bh[2], bl[2];
                ldsm_x4(ah, ahi0 + off);
                ldsm_x4(al, alo0 + off);
                ldsm_x2(bh, bhi0 + off);
                ldsm_x2(bl, blo0 + off);
                mma_bf16(c, ah, bh);
                mma_bf16(c, al, bh);
                mma_bf16(c, ah, bl);
            }
        }

        // scatter to gbuf[r][b] (+ input gates)
        gbuf[(r0    ) * 17 + grp    ] = c[0] + gt0.x;
        gbuf[(r0 + 1) * 17 + grp    ] = c[1] + gt0.y;
        gbuf[(r0    ) * 17 + grp + 8] = c[2] + gt1.x;
        gbuf[(r0 + 1) * 17 + grp + 8] = c[3] + gt1.y;
        __syncthreads();

        // pointwise LSTM cell: thread -> (unit su, batch sb)
        {
            const float iv = gbuf[(0 * 8 + su) * 17 + sb];
            const float fv = gbuf[(1 * 8 + su) * 17 + sb];
            const float gv = gbuf[(2 * 8 + su) * 17 + sb];
            const float ov = gbuf[(3 * 8 + su) * 17 + sb];
            const float ig = 1.f / (1.f + expf(-iv));
            const float fg = 1.f / (1.f + expf(-fv));
            const float og = 1.f / (1.f + expf(-ov));
            const float cv = fg * cst[tid] + ig * tanhf(gv);
            cst[tid] = cv;
            const float h = og * tanhf(cv);
            __nv_bfloat16 hi, lo;
            bsplit(h, hi, lo);
            g_hhi[(t + 1) & 1][sb * HH + unit] = hi;
            g_hlo[(t + 1) & 1][sb * HH + unit] = lo;
            g_enc[((size_t)sb * SS + t) * HH + unit] = h;
        }
        __threadfence();
        __syncthreads();
        if (tid == 0) g_flags[cta] = base + t + 1;
    }
}

// ============ block reduction helper (256 threads) ============
__device__ __forceinline__ float blk_sum256(float v, float* red)
{
#pragma unroll
    for (int o = 16; o > 0; o >>= 1) v += __shfl_down_sync(0xffffffffu, v, o);
    const int tid = threadIdx.x;
    if ((tid & 31) == 0) red[tid >> 5] = v;
    __syncthreads();
    if (tid < 32) {
        float x = (tid < 8) ? red[tid] : 0.f;
#pragma unroll
        for (int o = 4; o > 0; o >>= 1) x += __shfl_down_sync(0xffffffffu, x, o);
        if (tid == 0) red[0] = x;
    }
    __syncthreads();
    const float s = red[0];
    __syncthreads();
    return s;
}

// ============ span mean-pool + LayerNorm ============
__global__ void pool_ln_kernel(const float* __restrict__ gamma, const float* __restrict__ beta,
                               const int* __restrict__ heads, const int* __restrict__ tails)
{
    __shared__ float red[32];
    const int span = blockIdx.x;
    const int tid = threadIdx.x;
    const int b = span >> 5;
    const int head = heads[span], tail = tails[span];

    float4 acc = make_float4(0.f, 0.f, 0.f, 0.f);
    for (int s = head + 1; s < tail; s++) {
        const float4 v = *(const float4*)(g_enc + ((size_t)b * SS + s) * HH + tid * 4);
        acc.x += v.x; acc.y += v.y; acc.z += v.z; acc.w += v.w;
    }
    const float invc = 1.f / (float)(tail - head - 1);
    acc.x *= invc; acc.y *= invc; acc.z *= invc; acc.w *= invc;

    const float mu = blk_sum256(acc.x + acc.y + acc.z + acc.w, red) * (1.f / HH);
    const float dx = acc.x - mu, dy = acc.y - mu, dz = acc.z - mu, dw = acc.w - mu;
    const float var = blk_sum256(dx*dx + dy*dy + dz*dz + dw*dw, red) * (1.f / HH);
    const float rstd = rsqrtf(var + 1e-7f);

    const int h = tid * 4;
    const float4 gm = *(const float4*)(gamma + h);
    const float4 bt = *(const float4*)(beta + h);
    float4 o = make_float4(dx*rstd*gm.x + bt.x, dy*rstd*gm.y + bt.y,
                           dz*rstd*gm.z + bt.z, dw*rstd*gm.w + bt.w);
    *(float4*)(g_pool + (size_t)span * HH + h) = o;
}

// ============ residual LayerNorm ============
__global__ void ln_res_kernel(const float* __restrict__ gamma, const float* __restrict__ beta)
{
    __shared__ float red[32];
    const int row = blockIdx.x;
    const int tid = threadIdx.x;
    const size_t off = (size_t)row * HH + tid * 4;

    float4 x = *(const float4*)(g_wo + off);
    const float4 p = *(const float4*)(g_pool + off);
    x.x += p.x; x.y += p.y; x.z += p.z; x.w += p.w;

    const float mu = blk_sum256(x.x + x.y + x.z + x.w, red) * (1.f / HH);
    const float dx = x.x - mu, dy = x.y - mu, dz = x.z - mu, dw = x.w - mu;
    const float var = blk_sum256(dx*dx + dy*dy + dz*dz + dw*dw, red) * (1.f / HH);
    const float rstd = rsqrtf(var + 1e-7f);

    const int h = tid * 4;
    const float4 gm = *(const float4*)(gamma + h);
    const float4 bt = *(const float4*)(beta + h);
    float4 o = make_float4(dx*rstd*gm.x + bt.x, dy*rstd*gm.y + bt.y,
                           dz*rstd*gm.z + bt.z, dw*rstd*gm.w + bt.w);
    *(float4*)(g_attn + off) = o;
}

// ============ span attention: one CTA per (b, head) ============
__global__ void attn_kernel(const int* __restrict__ mask)
{
    __shared__ float Qs[32][65], Ks[32][65], Vs[32][65];
    __shared__ float P[32][33];
    __shared__ int ms[32];

    const int bh = blockIdx.x;
    const int b = bh / NHEADS, hd = bh % NHEADS;
    const int tid = threadIdx.x;
    const size_t rowbase = (size_t)b * NSPAN;
    const int col0 = hd * DHEAD;

    for (int i = tid; i < NSPAN * DHEAD; i += 128) {
        const int n = i >> 6, d = i & 63;
        const size_t off = (rowbase + n) * HH + col0 + d;
        Qs[n][d] = g_q[off];
        Ks[n][d] = g_k[off];
        Vs[n][d] = g_v[off];
    }
    if (tid < 32) ms[tid] = mask[b * NSPAN + tid];
    __syncthreads();

    for (int i = tid; i < 1024; i += 128) {
        const int qi = i >> 5, kj = i & 31;
        float s = 0.f;
#pragma unroll
        for (int d = 0; d < 64; d++) s += Qs[qi][d] * Ks[kj][d];
        s *= 0.125f;
        P[qi][kj] = (ms[qi] && ms[kj]) ? s : -3.402823466e38f;
    }
    __syncthreads();

    if (tid < 32) {
        float mx = -3.402823466e38f;
#pragma unroll
        for (int j = 0; j < 32; j++) mx = fmaxf(mx, P[tid][j]);
        float sum = 0.f;
#pragma unroll
        for (int j = 0; j < 32; j++) { float e = expf(P[tid][j] - mx); P[tid][j] = e; sum += e; }
        const float inv = 1.f / sum;
#pragma unroll
        for (int j = 0; j < 32; j++) P[tid][j] = (ms[tid] && ms[j]) ? P[tid][j] * inv : 0.f;
    }
    __syncthreads();

    for (int i = tid; i < NSPAN * DHEAD; i += 128) {
        const int qi = i >> 6, d = i & 63;
        float s = 0.f;
#pragma unroll
        for (int j = 0; j < 32; j++) s += P[qi][j] * Vs[j][d];
        g_ctx[(rowbase + qi) * HH + col0 + d] = s;
    }
}

// ============ launch ============
extern "C" void kernel_launch(void* const* d_in, const int* in_sizes, int n_in,
                              void* d_out, int out_size)
{
    const float* enc_in  = (const float*)d_in[0];
    const float* W_ih    = (const float*)d_in[1];
    const float* W_hh    = (const float*)d_in[2];
    const float* b_ih    = (const float*)d_in[3];
    const float* b_hh    = (const float*)d_in[4];
    const float* ln_g    = (const float*)d_in[5];
    const float* ln_b    = (const float*)d_in[6];
    const float* Wq      = (const float*)d_in[7];
    const float* bq      = (const float*)d_in[8];
    const float* Wk      = (const float*)d_in[9];
    const float* bk      = (const float*)d_in[10];
    const float* Wv      = (const float*)d_in[11];
    const float* bv      = (const float*)d_in[12];
    const float* Wo      = (const float*)d_in[13];
    const float* bo      = (const float*)d_in[14];
    const float* aln_g   = (const float*)d_in[15];
    const float* aln_b   = (const float*)d_in[16];
    const float* clf_W   = (const float*)d_in[17];
    const float* clf_b   = (const float*)d_in[18];
    const int*   heads   = (const int*)d_in[19];
    const int*   tails   = (const int*)d_in[20];
    const int*   mask    = (const int*)d_in[21];
    float* out = (float*)d_out;

    float *gates, *pool, *q, *k, *v, *ctx, *wo_buf, *attn;
    cudaGetSymbolAddress((void**)&gates,  g_gates);
    cudaGetSymbolAddress((void**)&pool,   g_pool);
    cudaGetSymbolAddress((void**)&q,      g_q);
    cudaGetSymbolAddress((void**)&k,      g_k);
    cudaGetSymbolAddress((void**)&v,      g_v);
    cudaGetSymbolAddress((void**)&ctx,    g_ctx);
    cudaGetSymbolAddress((void**)&wo_buf, g_wo);
    cudaGetSymbolAddress((void**)&attn,   g_attn);

    // 1. gates = X @ W_ih^T + b_ih + b_hh   (tf32 tensor cores)
    mma_gemm_nt<<<dim3(HX4 / 128, (BB * SS) / 128), 256>>>(
        enc_in, W_ih, b_ih, b_hh, gates, BB * SS, HX4, HH);

    // 2. persistent LSTM (split-bf16 mma recurrent GEMM)
    const int smem = (32 * WSTRIDE * 2 + 16 * WSTRIDE * 2) * (int)sizeof(__nv_bfloat16)
                   + (32 * 17 + 128) * (int)sizeof(float);
    cudaFuncSetAttribute(lstm_kernel, cudaFuncAttributeMaxDynamicSharedMemorySize, smem);
    lstm_kernel<<<NCTA, 128, smem>>>(W_hh);

    // 3. span pool + LN
    pool_ln_kernel<<<BB * NSPAN, 256>>>(ln_g, ln_b, heads, tails);

    // 4. QKV projections (tf32)
    mma_gemm_nt<<<dim3(HH / 128, (BB * NSPAN) / 128), 256>>>(pool, Wq, bq, nullptr, q, BB * NSPAN, HH, HH);
    mma_gemm_nt<<<dim3(HH / 128, (BB * NSPAN) / 128), 256>>>(pool, Wk, bk, nullptr, k, BB * NSPAN, HH, HH);
    mma_gemm_nt<<<dim3(HH / 128, (BB * NSPAN) / 128), 256>>>(pool, Wv, bv, nullptr, v, BB * NSPAN, HH, HH);

    // 5. attention
    attn_kernel<<<BB * NHEADS, 128>>>(mask);

    // 6. output projection (tf32)
    mma_gemm_nt<<<dim3(HH / 128, (BB * NSPAN) / 128), 256>>>(ctx, Wo, bo, nullptr, wo_buf, BB * NSPAN, HH, HH);

    // 7. residual LN
    ln_res_kernel<<<BB * NSPAN, 256>>>(aln_g, aln_b);

    // 8. classifier -> d_out [B,NS,L]
    sgemm_nt<<<dim3(1, (BB * NSPAN) / 128), 256>>>(attn, clf_W, clf_b, out, BB * NSPAN, NCLS, HH);
}

// round 6
// speedup vs baseline: 2.2230x; 1.2738x over previous
#include <cuda_runtime.h>
#include <cuda_bf16.h>
#include <math.h>
#include <stdint.h>

#define BB      16
#define SS      1024
#define HH      1024
#define HX4     4096
#define NSPAN   32
#define NHEADS  16
#define DHEAD   64
#define NCLS    5
#define NCTA    128
#define UPC     8
#define WSTRIDE 1032   // padded bf16 row stride -> conflict-free ldmatrix

// ---------------- device scratch ----------------
__device__ float g_gates[(size_t)BB * SS * HX4];
__device__ float g_enc  [(size_t)BB * SS * HH];
__device__ __nv_bfloat16 g_hhi[2][BB * HH];
__device__ __nv_bfloat16 g_hlo[2][BB * HH];
__device__ int g_flags[NCTA];
__device__ float g_pool [BB * NSPAN * HH];
__device__ float g_q    [BB * NSPAN * HH];
__device__ float g_k    [BB * NSPAN * HH];
__device__ float g_v    [BB * NSPAN * HH];
__device__ float g_ctx  [BB * NSPAN * HH];
__device__ float g_wo   [BB * NSPAN * HH];
__device__ float g_attn [BB * NSPAN * HH];

// ---------------- asm helpers ----------------
__device__ __forceinline__ uint32_t f2tf32(float x) {
    uint32_t r; asm("cvt.rna.tf32.f32 %0, %1;" : "=r"(r) : "f"(x)); return r;
}
__device__ __forceinline__ void mma_tf32(float* c, const uint32_t* a, const uint32_t* b) {
    asm volatile("mma.sync.aligned.m16n8k8.row.col.f32.tf32.tf32.f32 "
        "{%0,%1,%2,%3}, {%4,%5,%6,%7}, {%8,%9}, {%0,%1,%2,%3};"
        : "+f"(c[0]), "+f"(c[1]), "+f"(c[2]), "+f"(c[3])
        : "r"(a[0]), "r"(a[1]), "r"(a[2]), "r"(a[3]), "r"(b[0]), "r"(b[1]));
}
__device__ __forceinline__ void mma_bf16(float* c, const uint32_t* a, const uint32_t* b) {
    asm volatile("mma.sync.aligned.m16n8k16.row.col.f32.bf16.bf16.f32 "
        "{%0,%1,%2,%3}, {%4,%5,%6,%7}, {%8,%9}, {%0,%1,%2,%3};"
        : "+f"(c[0]), "+f"(c[1]), "+f"(c[2]), "+f"(c[3])
        : "r"(a[0]), "r"(a[1]), "r"(a[2]), "r"(a[3]), "r"(b[0]), "r"(b[1]));
}
__device__ __forceinline__ void ldsm_x4(uint32_t* r, uint32_t addr) {
    asm volatile("ldmatrix.sync.aligned.m8n8.x4.shared.b16 {%0,%1,%2,%3}, [%4];"
        : "=r"(r[0]), "=r"(r[1]), "=r"(r[2]), "=r"(r[3]) : "r"(addr));
}
__device__ __forceinline__ void ldsm_x2(uint32_t* r, uint32_t addr) {
    asm volatile("ldmatrix.sync.aligned.m8n8.x2.shared.b16 {%0,%1}, [%2];"
        : "=r"(r[0]), "=r"(r[1]) : "r"(addr));
}
__device__ __forceinline__ uint32_t smem_u32(const void* p) {
    uint32_t a;
    asm("{ .reg .u64 t; cvta.to.shared.u64 t, %1; cvt.u32.u64 %0, t; }" : "=r"(a) : "l"(p));
    return a;
}
__device__ __forceinline__ void bsplit(float w, __nv_bfloat16& hi, __nv_bfloat16& lo) {
    hi = __float2bfloat16(w);
    lo = __float2bfloat16(w - __bfloat162float(hi));
}
__device__ __forceinline__ int ld_acq(const int* p) {
    int v; asm volatile("ld.acquire.gpu.global.b32 %0, [%1];" : "=r"(v) : "l"(p)); return v;
}
__device__ __forceinline__ void st_rlx(int* p, int v) {
    asm volatile("st.relaxed.gpu.global.b32 [%0], %1;" :: "l"(p), "r"(v) : "memory");
}
__device__ __forceinline__ void cp16(uint32_t s, const void* g) {
    asm volatile("cp.async.cg.shared.global [%0], [%1], 16;" :: "r"(s), "l"(g));
}
#define CP_COMMIT() asm volatile("cp.async.commit_group;" ::: "memory")
#define CP_WAIT1()  asm volatile("cp.async.wait_group 1;" ::: "memory")
#define CP_WAIT0()  asm volatile("cp.async.wait_group 0;" ::: "memory")

// =====================================================================
// tf32 tensor-core GEMM body (software-pipelined k-slabs).
// C[M,N] = A[M,K] @ W[N,K]^T + b1 (+ b2). M,N mult of 128, K mult of 16.
// =====================================================================
__device__ __forceinline__ void gemm_body(
    const float* __restrict__ A, const float* __restrict__ W,
    const float* __restrict__ b1, const float* __restrict__ b2,
    float* __restrict__ C, int N, int K,
    uint32_t (*As)[136], uint32_t (*Ws)[136])
{
    const int tid = threadIdx.x;
    const int lane = tid & 31, warp = tid >> 5;
    const int wm = (warp >> 2) * 64;
    const int wnn = (warp & 3) * 32;
    const int tig = lane & 3, grp = lane >> 2;

    const int n0 = blockIdx.x * 128, m0 = blockIdx.y * 128;
    const int lr = tid >> 1;
    const int kq = (tid & 1) * 8;

    float c[4][4][4];
#pragma unroll
    for (int mi = 0; mi < 4; mi++)
#pragma unroll
        for (int ni = 0; ni < 4; ni++)
#pragma unroll
            for (int j = 0; j < 4; j++) c[mi][ni][j] = 0.f;

    const float* Ap = A + (size_t)(m0 + lr) * K + kq;
    const float* Wp = W + (size_t)(n0 + lr) * K + kq;

    float4 av0 = *(const float4*)(Ap);
    float4 av1 = *(const float4*)(Ap + 4);
    float4 wv0 = *(const float4*)(Wp);
    float4 wv1 = *(const float4*)(Wp + 4);

    for (int k0 = 0; k0 < K; k0 += 16) {
        As[kq+0][lr] = f2tf32(av0.x); As[kq+1][lr] = f2tf32(av0.y);
        As[kq+2][lr] = f2tf32(av0.z); As[kq+3][lr] = f2tf32(av0.w);
        As[kq+4][lr] = f2tf32(av1.x); As[kq+5][lr] = f2tf32(av1.y);
        As[kq+6][lr] = f2tf32(av1.z); As[kq+7][lr] = f2tf32(av1.w);
        Ws[kq+0][lr] = f2tf32(wv0.x); Ws[kq+1][lr] = f2tf32(wv0.y);
        Ws[kq+2][lr] = f2tf32(wv0.z); Ws[kq+3][lr] = f2tf32(wv0.w);
        Ws[kq+4][lr] = f2tf32(wv1.x); Ws[kq+5][lr] = f2tf32(wv1.y);
        Ws[kq+6][lr] = f2tf32(wv1.z); Ws[kq+7][lr] = f2tf32(wv1.w);
        __syncthreads();

        if (k0 + 16 < K) {
            av0 = *(const float4*)(Ap + k0 + 16);
            av1 = *(const float4*)(Ap + k0 + 20);
            wv0 = *(const float4*)(Wp + k0 + 16);
            wv1 = *(const float4*)(Wp + k0 + 20);
        }

#pragma unroll
        for (int ks = 0; ks < 16; ks += 8) {
            uint32_t a[4][4], b[4][2];
#pragma unroll
            for (int mi = 0; mi < 4; mi++) {
                const int rb = wm + mi * 16 + grp;
                a[mi][0] = As[ks + tig][rb];
                a[mi][1] = As[ks + tig][rb + 8];
                a[mi][2] = As[ks + tig + 4][rb];
                a[mi][3] = As[ks + tig + 4][rb + 8];
            }
#pragma unroll
            for (int ni = 0; ni < 4; ni++) {
                const int nb = wnn + ni * 8 + grp;
                b[ni][0] = Ws[ks + tig][nb];
                b[ni][1] = Ws[ks + tig + 4][nb];
            }
#pragma unroll
            for (int mi = 0; mi < 4; mi++)
#pragma unroll
                for (int ni = 0; ni < 4; ni++)
                    mma_tf32(c[mi][ni], a[mi], b[ni]);
        }
        __syncthreads();
    }

#pragma unroll
    for (int ni = 0; ni < 4; ni++) {
        const int col = n0 + wnn + ni * 8 + tig * 2;
        float bias0 = b1[col], bias1 = b1[col + 1];
        if (b2) { bias0 += b2[col]; bias1 += b2[col + 1]; }
#pragma unroll
        for (int mi = 0; mi < 4; mi++) {
            const int row = m0 + wm + mi * 16 + grp;
            C[(size_t)row * N + col]           = c[mi][ni][0] + bias0;
            C[(size_t)row * N + col + 1]       = c[mi][ni][1] + bias1;
            C[(size_t)(row + 8) * N + col]     = c[mi][ni][2] + bias0;
            C[(size_t)(row + 8) * N + col + 1] = c[mi][ni][3] + bias1;
        }
    }
}

__global__ void __launch_bounds__(256)
mma_gemm_nt(const float* __restrict__ A, const float* __restrict__ W,
            const float* __restrict__ b1, const float* __restrict__ b2,
            float* __restrict__ C, int N, int K)
{
    __shared__ uint32_t As[16][136];
    __shared__ uint32_t Ws[16][136];
    gemm_body(A, W, b1, b2, C, N, K, As, Ws);
}

// fused Q/K/V projections: blockIdx.z selects the matrix
__global__ void __launch_bounds__(256)
mma_gemm_qkv(const float* __restrict__ A,
             const float* __restrict__ Wq, const float* __restrict__ Wk, const float* __restrict__ Wv,
             const float* __restrict__ bq, const float* __restrict__ bk, const float* __restrict__ bv,
             float* __restrict__ Oq, float* __restrict__ Ok, float* __restrict__ Ov)
{
    __shared__ uint32_t As[16][136];
    __shared__ uint32_t Ws[16][136];
    const int z = blockIdx.z;
    const float* W = (z == 0) ? Wq : (z == 1) ? Wk : Wv;
    const float* b = (z == 0) ? bq : (z == 1) ? bk : bv;
    float* O       = (z == 0) ? Oq : (z == 1) ? Ok : Ov;
    gemm_body(A, W, b, nullptr, O, HH, HH, As, Ws);
}

// =====================================================================
// Persistent LSTM, split-bf16 tensor-core recurrent GEMM, pipelined.
// =====================================================================
__global__ void __launch_bounds__(128, 1)
lstm_kernel(const float* __restrict__ Whh)
{
    extern __shared__ char smraw[];
    __nv_bfloat16* Whi = (__nv_bfloat16*)smraw;
    __nv_bfloat16* Wlo = Whi + 32 * WSTRIDE;
    __nv_bfloat16* hhi = Wlo + 32 * WSTRIDE;
    __nv_bfloat16* hlo = hhi + 16 * WSTRIDE;
    float* gbuf = (float*)(hlo + 16 * WSTRIDE);
    float* cst  = gbuf + 32 * 17;

    const int tid = threadIdx.x;
    const int cta = blockIdx.x;
    const int lane = tid & 31, warp = tid >> 5;
    const int grp = lane >> 2, tig = lane & 3;

    // one-time: split W_hh slice into bf16 hi/lo in SMEM
    for (int i = tid; i < 32 * 1024; i += 128) {
        const int r = i >> 10, k = i & 1023;
        const int jrow = (r >> 3) * 1024 + cta * UPC + (r & 7);
        __nv_bfloat16 hi, lo;
        bsplit(Whh[(size_t)jrow * HH + k], hi, lo);
        Whi[r * WSTRIDE + k] = hi;
        Wlo[r * WSTRIDE + k] = lo;
    }
    cst[tid] = 0.f;
    const int base = g_flags[cta];    // own flag: race-free across replays
    __syncthreads();

    const uint32_t a_row = lane & 15;
    const uint32_t a_colB = (lane >> 4) * 16;
    const uint32_t ahi0 = smem_u32(hhi) + a_row * (WSTRIDE * 2) + a_colB;
    const uint32_t alo0 = smem_u32(hlo) + a_row * (WSTRIDE * 2) + a_colB;
    const uint32_t b_row = warp * 8 + (lane & 7);
    const uint32_t b_colB = ((lane >> 3) & 1) * 16;
    const uint32_t bhi0 = smem_u32(Whi) + b_row * (WSTRIDE * 2) + b_colB;
    const uint32_t blo0 = smem_u32(Wlo) + b_row * (WSTRIDE * 2) + b_colB;
    const uint32_t s_hhi = smem_u32(hhi), s_hlo = smem_u32(hlo);

    const int r0 = warp * 8 + tig * 2;
    const int jrow0 = warp * 1024 + cta * UPC + tig * 2;
    const int su = tid & 7, sb = tid >> 3;
    const int unit = cta * UPC + su;

    for (int t = 0; t < SS; t++) {
        // barrier-independent prefetch of input-gate contributions
        const float2 gt0 = *(const float2*)(g_gates + ((size_t)grp       * SS + t) * HX4 + jrow0);
        const float2 gt1 = *(const float2*)(g_gates + ((size_t)(grp + 8) * SS + t) * HX4 + jrow0);

        float c[4] = {0.f, 0.f, 0.f, 0.f};
        if (t > 0) {
            // grid barrier: acquire-poll all CTA flags (no sleep)
            if (tid < 32) {
                const unsigned tgt = (unsigned)(base + t);
                for (;;) {
                    const int v0 = ld_acq(&g_flags[tid]);
                    const int v1 = ld_acq(&g_flags[tid + 32]);
                    const int v2 = ld_acq(&g_flags[tid + 64]);
                    const int v3 = ld_acq(&g_flags[tid + 96]);
                    const bool ok =
                        (int)((unsigned)v0 - tgt) >= 0 && (int)((unsigned)v1 - tgt) >= 0 &&
                        (int)((unsigned)v2 - tgt) >= 0 && (int)((unsigned)v3 - tgt) >= 0;
                    if (__all_sync(0xffffffffu, ok)) break;
                }
            }
            __syncthreads();

            // stage h_{t-1} in two pipelined halves via cp.async
            const __nv_bfloat16* shi = g_hhi[t & 1];
            const __nv_bfloat16* slo = g_hlo[t & 1];
#pragma unroll
            for (int ph = 0; ph < 2; ph++) {
                for (int i = tid; i < 1024; i += 128) {
                    const int row = i >> 6;
                    const int c8 = (i & 63) * 8 + ph * 512;
                    cp16(s_hhi + row * (WSTRIDE * 2) + c8 * 2, shi + row * 1024 + c8);
                    cp16(s_hlo + row * (WSTRIDE * 2) + c8 * 2, slo + row * 1024 + c8);
                }
                CP_COMMIT();
            }
            CP_WAIT1();
            __syncthreads();
#pragma unroll 4
            for (int kt = 0; kt < 32; kt++) {
                const uint32_t off = kt * 32;
                uint32_t ah[4], al[4], bh[2], bl[2];
                ldsm_x4(ah, ahi0 + off);
                ldsm_x4(al, alo0 + off);
                ldsm_x2(bh, bhi0 + off);
                ldsm_x2(bl, blo0 + off);
                mma_bf16(c, ah, bh);
                mma_bf16(c, al, bh);
                mma_bf16(c, ah, bl);
            }
            CP_WAIT0();
            __syncthreads();
#pragma unroll 4
            for (int kt = 32; kt < 64; kt++) {
                const uint32_t off = kt * 32;
                uint32_t ah[4], al[4], bh[2], bl[2];
                ldsm_x4(ah, ahi0 + off);
                ldsm_x4(al, alo0 + off);
                ldsm_x2(bh, bhi0 + off);
                ldsm_x2(bl, blo0 + off);
                mma_bf16(c, ah, bh);
                mma_bf16(c, al, bh);
                mma_bf16(c, ah, bl);
            }
        }

        gbuf[(r0    ) * 17 + grp    ] = c[0] + gt0.x;
        gbuf[(r0 + 1) * 17 + grp    ] = c[1] + gt0.y;
        gbuf[(r0    ) * 17 + grp + 8] = c[2] + gt1.x;
        gbuf[(r0 + 1) * 17 + grp + 8] = c[3] + gt1.y;
        __syncthreads();

        float h;
        {
            const float iv = gbuf[(0 * 8 + su) * 17 + sb];
            const float fv = gbuf[(1 * 8 + su) * 17 + sb];
            const float gv = gbuf[(2 * 8 + su) * 17 + sb];
            const float ov = gbuf[(3 * 8 + su) * 17 + sb];
            const float ig = 1.f / (1.f + expf(-iv));
            const float fg = 1.f / (1.f + expf(-fv));
            const float og = 1.f / (1.f + expf(-ov));
            const float cv = fg * cst[tid] + ig * tanhf(gv);
            cst[tid] = cv;
            h = og * tanhf(cv);
            __nv_bfloat16 hi, lo;
            bsplit(h, hi, lo);
            g_hhi[(t + 1) & 1][sb * HH + unit] = hi;
            g_hlo[(t + 1) & 1][sb * HH + unit] = lo;
        }
        __threadfence();
        __syncthreads();
        if (tid == 0) st_rlx(&g_flags[cta], base + t + 1);
        g_enc[((size_t)sb * SS + t) * HH + unit] = h;   // off the critical path
    }
}

// ============ block reduction helper (256 threads) ============
__device__ __forceinline__ float blk_sum256(float v, float* red)
{
#pragma unroll
    for (int o = 16; o > 0; o >>= 1) v += __shfl_down_sync(0xffffffffu, v, o);
    const int tid = threadIdx.x;
    if ((tid & 31) == 0) red[tid >> 5] = v;
    __syncthreads();
    if (tid < 32) {
        float x = (tid < 8) ? red[tid] : 0.f;
#pragma unroll
        for (int o = 4; o > 0; o >>= 1) x += __shfl_down_sync(0xffffffffu, x, o);
        if (tid == 0) red[0] = x;
    }
    __syncthreads();
    const float s = red[0];
    __syncthreads();
    return s;
}

// ============ span mean-pool + LayerNorm ============
__global__ void pool_ln_kernel(const float* __restrict__ gamma, const float* __restrict__ beta,
                               const int* __restrict__ heads, const int* __restrict__ tails)
{
    __shared__ float red[32];
    const int span = blockIdx.x;
    const int tid = threadIdx.x;
    const int b = span >> 5;
    const int head = heads[span], tail = tails[span];

    float4 acc = make_float4(0.f, 0.f, 0.f, 0.f);
    for (int s = head + 1; s < tail; s++) {
        const float4 v = *(const float4*)(g_enc + ((size_t)b * SS + s) * HH + tid * 4);
        acc.x += v.x; acc.y += v.y; acc.z += v.z; acc.w += v.w;
    }
    const float invc = 1.f / (float)(tail - head - 1);
    acc.x *= invc; acc.y *= invc; acc.z *= invc; acc.w *= invc;

    const float mu = blk_sum256(acc.x + acc.y + acc.z + acc.w, red) * (1.f / HH);
    const float dx = acc.x - mu, dy = acc.y - mu, dz = acc.z - mu, dw = acc.w - mu;
    const float var = blk_sum256(dx*dx + dy*dy + dz*dz + dw*dw, red) * (1.f / HH);
    const float rstd = rsqrtf(var + 1e-7f);

    const int h = tid * 4;
    const float4 gm = *(const float4*)(gamma + h);
    const float4 bt = *(const float4*)(beta + h);
    float4 o = make_float4(dx*rstd*gm.x + bt.x, dy*rstd*gm.y + bt.y,
                           dz*rstd*gm.z + bt.z, dw*rstd*gm.w + bt.w);
    *(float4*)(g_pool + (size_t)span * HH + h) = o;
}

// ============ residual LayerNorm ============
__global__ void ln_res_kernel(const float* __restrict__ gamma, const float* __restrict__ beta)
{
    __shared__ float red[32];
    const int row = blockIdx.x;
    const int tid = threadIdx.x;
    const size_t off = (size_t)row * HH + tid * 4;

    float4 x = *(const float4*)(g_wo + off);
    const float4 p = *(const float4*)(g_pool + off);
    x.x += p.x; x.y += p.y; x.z += p.z; x.w += p.w;

    const float mu = blk_sum256(x.x + x.y + x.z + x.w, red) * (1.f / HH);
    const float dx = x.x - mu, dy = x.y - mu, dz = x.z - mu, dw = x.w - mu;
    const float var = blk_sum256(dx*dx + dy*dy + dz*dz + dw*dw, red) * (1.f / HH);
    const float rstd = rsqrtf(var + 1e-7f);

    const int h = tid * 4;
    const float4 gm = *(const float4*)(gamma + h);
    const float4 bt = *(const float4*)(beta + h);
    float4 o = make_float4(dx*rstd*gm.x + bt.x, dy*rstd*gm.y + bt.y,
                           dz*rstd*gm.z + bt.z, dw*rstd*gm.w + bt.w);
    *(float4*)(g_attn + off) = o;
}

// ============ span attention: one CTA per (b, head) ============
__global__ void attn_kernel(const int* __restrict__ mask)
{
    __shared__ float Qs[32][65], Ks[32][65], Vs[32][65];
    __shared__ float P[32][33];
    __shared__ int ms[32];

    const int bh = blockIdx.x;
    const int b = bh / NHEADS, hd = bh % NHEADS;
    const int tid = threadIdx.x;
    const size_t rowbase = (size_t)b * NSPAN;
    const int col0 = hd * DHEAD;

    for (int i = tid; i < NSPAN * DHEAD; i += 128) {
        const int n = i >> 6, d = i & 63;
        const size_t off = (rowbase + n) * HH + col0 + d;
        Qs[n][d] = g_q[off];
        Ks[n][d] = g_k[off];
        Vs[n][d] = g_v[off];
    }
    if (tid < 32) ms[tid] = mask[b * NSPAN + tid];
    __syncthreads();

    for (int i = tid; i < 1024; i += 128) {
        const int qi = i >> 5, kj = i & 31;
        float s = 0.f;
#pragma unroll
        for (int d = 0; d < 64; d++) s += Qs[qi][d] * Ks[kj][d];
        s *= 0.125f;
        P[qi][kj] = (ms[qi] && ms[kj]) ? s : -3.402823466e38f;
    }
    __syncthreads();

    if (tid < 32) {
        float mx = -3.402823466e38f;
#pragma unroll
        for (int j = 0; j < 32; j++) mx = fmaxf(mx, P[tid][j]);
        float sum = 0.f;
#pragma unroll
        for (int j = 0; j < 32; j++) { float e = expf(P[tid][j] - mx); P[tid][j] = e; sum += e; }
        const float inv = 1.f / sum;
#pragma unroll
        for (int j = 0; j < 32; j++) P[tid][j] = (ms[tid] && ms[j]) ? P[tid][j] * inv : 0.f;
    }
    __syncthreads();

    for (int i = tid; i < NSPAN * DHEAD; i += 128) {
        const int qi = i >> 6, d = i & 63;
        float s = 0.f;
#pragma unroll
        for (int j = 0; j < 32; j++) s += P[qi][j] * Vs[j][d];
        g_ctx[(rowbase + qi) * HH + col0 + d] = s;
    }
}

// ============ classifier: warp per row, N=5 ============
__global__ void __launch_bounds__(256)
clf_kernel(const float* __restrict__ W, const float* __restrict__ b, float* __restrict__ out)
{
    __shared__ float ws[NCLS * HH];
    const int tid = threadIdx.x;
    for (int i = tid; i < NCLS * HH; i += 256) ws[i] = W[i];
    __syncthreads();

    const int warp = tid >> 5, lane = tid & 31;
    const int row = blockIdx.x * 8 + warp;
    const float* a = g_attn + (size_t)row * HH;

    float acc[NCLS] = {0.f, 0.f, 0.f, 0.f, 0.f};
    for (int k = lane; k < HH; k += 32) {
        const float av = a[k];
#pragma unroll
        for (int c = 0; c < NCLS; c++) acc[c] += av * ws[c * HH + k];
    }
#pragma unroll
    for (int c = 0; c < NCLS; c++) {
#pragma unroll
        for (int o = 16; o > 0; o >>= 1) acc[c] += __shfl_down_sync(0xffffffffu, acc[c], o);
    }
    if (lane == 0) {
#pragma unroll
        for (int c = 0; c < NCLS; c++) out[(size_t)row * NCLS + c] = acc[c] + b[c];
    }
}

// ============ launch ============
extern "C" void kernel_launch(void* const* d_in, const int* in_sizes, int n_in,
                              void* d_out, int out_size)
{
    const float* enc_in  = (const float*)d_in[0];
    const float* W_ih    = (const float*)d_in[1];
    const float* W_hh    = (const float*)d_in[2];
    const float* b_ih    = (const float*)d_in[3];
    const float* b_hh    = (const float*)d_in[4];
    const float* ln_g    = (const float*)d_in[5];
    const float* ln_b    = (const float*)d_in[6];
    const float* Wq      = (const float*)d_in[7];
    const float* bq      = (const float*)d_in[8];
    const float* Wk      = (const float*)d_in[9];
    const float* bk      = (const float*)d_in[10];
    const float* Wv      = (const float*)d_in[11];
    const float* bv      = (const float*)d_in[12];
    const float* Wo      = (const float*)d_in[13];
    const float* bo      = (const float*)d_in[14];
    const float* aln_g   = (const float*)d_in[15];
    const float* aln_b   = (const float*)d_in[16];
    const float* clf_W   = (const float*)d_in[17];
    const float* clf_b   = (const float*)d_in[18];
    const int*   heads   = (const int*)d_in[19];
    const int*   tails   = (const int*)d_in[20];
    const int*   mask    = (const int*)d_in[21];
    float* out = (float*)d_out;

    float *gates, *pool, *q, *k, *v, *ctx, *wo_buf;
    cudaGetSymbolAddress((void**)&gates,  g_gates);
    cudaGetSymbolAddress((void**)&pool,   g_pool);
    cudaGetSymbolAddress((void**)&q,      g_q);
    cudaGetSymbolAddress((void**)&k,      g_k);
    cudaGetSymbolAddress((void**)&v,      g_v);
    cudaGetSymbolAddress((void**)&ctx,    g_ctx);
    cudaGetSymbolAddress((void**)&wo_buf, g_wo);

    // 1. gates = X @ W_ih^T + b_ih + b_hh   (tf32, pipelined)
    mma_gemm_nt<<<dim3(HX4 / 128, (BB * SS) / 128), 256>>>(
        enc_in, W_ih, b_ih, b_hh, gates, HX4, HH);

    // 2. persistent LSTM
    const int smem = (32 * WSTRIDE * 2 + 16 * WSTRIDE * 2) * (int)sizeof(__nv_bfloat16)
                   + (32 * 17 + 128) * (int)sizeof(float);
    cudaFuncSetAttribute(lstm_kernel, cudaFuncAttributeMaxDynamicSharedMemorySize, smem);
    lstm_kernel<<<NCTA, 128, smem>>>(W_hh);

    // 3. span pool + LN
    pool_ln_kernel<<<BB * NSPAN, 256>>>(ln_g, ln_b, heads, tails);

    // 4. fused QKV projections (tf32)
    mma_gemm_qkv<<<dim3(HH / 128, (BB * NSPAN) / 128, 3), 256>>>(
        pool, Wq, Wk, Wv, bq, bk, bv, q, k, v);

    // 5. attention
    attn_kernel<<<BB * NHEADS, 128>>>(mask);

    // 6. output projection (tf32)
    mma_gemm_nt<<<dim3(HH / 128, (BB * NSPAN) / 128), 256>>>(ctx, Wo, bo, nullptr, wo_buf, HH, HH);

    // 7. residual LN
    ln_res_kernel<<<BB * NSPAN, 256>>>(aln_g, aln_b);

    // 8. classifier -> d_out [B,NS,L]
    clf_kernel<<<(BB * NSPAN) / 8, 256>>>(clf_W, clf_b, out);
}

// round 7
// speedup vs baseline: 2.5422x; 1.1436x over previous
#include <cuda_runtime.h>
#include <cuda_bf16.h>
#include <math.h>
#include <stdint.h>

#define BB      16
#define SS      1024
#define HH      1024
#define HX4     4096
#define NSPAN   32
#define NHEADS  16
#define DHEAD   64
#define NCLS    5
#define NCTA    128
#define UPC     8
#define WSTRIDE 1032   // padded bf16 row stride -> conflict-free ldmatrix

// ---------------- device scratch ----------------
__device__ float g_gates[(size_t)BB * SS * HX4];
__device__ float g_enc  [(size_t)BB * SS * HH];
__device__ __nv_bfloat16 g_hhi[2][BB * HH];
__device__ __nv_bfloat16 g_hlo[2][BB * HH];
__device__ int g_cnt[4 * 32];                 // 4 counters, 128B apart
__device__ float g_pool [BB * NSPAN * HH];
__device__ float g_q    [BB * NSPAN * HH];
__device__ float g_k    [BB * NSPAN * HH];
__device__ float g_v    [BB * NSPAN * HH];
__device__ float g_ctx  [BB * NSPAN * HH];
__device__ float g_wo   [BB * NSPAN * HH];
__device__ float g_attn [BB * NSPAN * HH];

// ---------------- asm helpers ----------------
__device__ __forceinline__ uint32_t f2tf32(float x) {
    uint32_t r; asm("cvt.rna.tf32.f32 %0, %1;" : "=r"(r) : "f"(x)); return r;
}
__device__ __forceinline__ void mma_tf32(float* c, const uint32_t* a, const uint32_t* b) {
    asm volatile("mma.sync.aligned.m16n8k8.row.col.f32.tf32.tf32.f32 "
        "{%0,%1,%2,%3}, {%4,%5,%6,%7}, {%8,%9}, {%0,%1,%2,%3};"
        : "+f"(c[0]), "+f"(c[1]), "+f"(c[2]), "+f"(c[3])
        : "r"(a[0]), "r"(a[1]), "r"(a[2]), "r"(a[3]), "r"(b[0]), "r"(b[1]));
}
__device__ __forceinline__ void mma_bf16(float* c, const uint32_t* a, const uint32_t* b) {
    asm volatile("mma.sync.aligned.m16n8k16.row.col.f32.bf16.bf16.f32 "
        "{%0,%1,%2,%3}, {%4,%5,%6,%7}, {%8,%9}, {%0,%1,%2,%3};"
        : "+f"(c[0]), "+f"(c[1]), "+f"(c[2]), "+f"(c[3])
        : "r"(a[0]), "r"(a[1]), "r"(a[2]), "r"(a[3]), "r"(b[0]), "r"(b[1]));
}
__device__ __forceinline__ void ldsm_x4(uint32_t* r, uint32_t addr) {
    asm volatile("ldmatrix.sync.aligned.m8n8.x4.shared.b16 {%0,%1,%2,%3}, [%4];"
        : "=r"(r[0]), "=r"(r[1]), "=r"(r[2]), "=r"(r[3]) : "r"(addr));
}
__device__ __forceinline__ void ldsm_x2(uint32_t* r, uint32_t addr) {
    asm volatile("ldmatrix.sync.aligned.m8n8.x2.shared.b16 {%0,%1}, [%2];"
        : "=r"(r[0]), "=r"(r[1]) : "r"(addr));
}
__device__ __forceinline__ uint32_t smem_u32(const void* p) {
    uint32_t a;
    asm("{ .reg .u64 t; cvta.to.shared.u64 t, %1; cvt.u32.u64 %0, t; }" : "=r"(a) : "l"(p));
    return a;
}
__device__ __forceinline__ void bsplit(float w, __nv_bfloat16& hi, __nv_bfloat16& lo) {
    hi = __float2bfloat16(w);
    lo = __float2bfloat16(w - __bfloat162float(hi));
}
__device__ __forceinline__ int ld_acq(const int* p) {
    int v; asm volatile("ld.acquire.gpu.global.b32 %0, [%1];" : "=r"(v) : "l"(p)); return v;
}
__device__ __forceinline__ void red_add_release(int* p, int v) {
    asm volatile("red.release.gpu.global.add.s32 [%0], %1;" :: "l"(p), "r"(v) : "memory");
}
__device__ __forceinline__ void cp16(uint32_t s, const void* g) {
    asm volatile("cp.async.cg.shared.global [%0], [%1], 16;" :: "r"(s), "l"(g));
}
#define CP_COMMIT() asm volatile("cp.async.commit_group;" ::: "memory")
#define CP_WAIT(n)  asm volatile("cp.async.wait_group %0;" :: "n"(n) : "memory")

// counter reset: keeps graph replays deterministic
__global__ void reset_kernel()
{
    if (threadIdx.x < 4) g_cnt[threadIdx.x * 32] = 0;
}

// =====================================================================
// tf32 tensor-core GEMM body (software-pipelined k-slabs).
// =====================================================================
__device__ __forceinline__ void gemm_body(
    const float* __restrict__ A, const float* __restrict__ W,
    const float* __restrict__ b1, const float* __restrict__ b2,
    float* __restrict__ C, int N, int K,
    uint32_t (*As)[136], uint32_t (*Ws)[136])
{
    const int tid = threadIdx.x;
    const int lane = tid & 31, warp = tid >> 5;
    const int wm = (warp >> 2) * 64;
    const int wnn = (warp & 3) * 32;
    const int tig = lane & 3, grp = lane >> 2;

    const int n0 = blockIdx.x * 128, m0 = blockIdx.y * 128;
    const int lr = tid >> 1;
    const int kq = (tid & 1) * 8;

    float c[4][4][4];
#pragma unroll
    for (int mi = 0; mi < 4; mi++)
#pragma unroll
        for (int ni = 0; ni < 4; ni++)
#pragma unroll
            for (int j = 0; j < 4; j++) c[mi][ni][j] = 0.f;

    const float* Ap = A + (size_t)(m0 + lr) * K + kq;
    const float* Wp = W + (size_t)(n0 + lr) * K + kq;

    float4 av0 = *(const float4*)(Ap);
    float4 av1 = *(const float4*)(Ap + 4);
    float4 wv0 = *(const float4*)(Wp);
    float4 wv1 = *(const float4*)(Wp + 4);

    for (int k0 = 0; k0 < K; k0 += 16) {
        As[kq+0][lr] = f2tf32(av0.x); As[kq+1][lr] = f2tf32(av0.y);
        As[kq+2][lr] = f2tf32(av0.z); As[kq+3][lr] = f2tf32(av0.w);
        As[kq+4][lr] = f2tf32(av1.x); As[kq+5][lr] = f2tf32(av1.y);
        As[kq+6][lr] = f2tf32(av1.z); As[kq+7][lr] = f2tf32(av1.w);
        Ws[kq+0][lr] = f2tf32(wv0.x); Ws[kq+1][lr] = f2tf32(wv0.y);
        Ws[kq+2][lr] = f2tf32(wv0.z); Ws[kq+3][lr] = f2tf32(wv0.w);
        Ws[kq+4][lr] = f2tf32(wv1.x); Ws[kq+5][lr] = f2tf32(wv1.y);
        Ws[kq+6][lr] = f2tf32(wv1.z); Ws[kq+7][lr] = f2tf32(wv1.w);
        __syncthreads();

        if (k0 + 16 < K) {
            av0 = *(const float4*)(Ap + k0 + 16);
            av1 = *(const float4*)(Ap + k0 + 20);
            wv0 = *(const float4*)(Wp + k0 + 16);
            wv1 = *(const float4*)(Wp + k0 + 20);
        }

#pragma unroll
        for (int ks = 0; ks < 16; ks += 8) {
            uint32_t a[4][4], b[4][2];
#pragma unroll
            for (int mi = 0; mi < 4; mi++) {
                const int rb = wm + mi * 16 + grp;
                a[mi][0] = As[ks + tig][rb];
                a[mi][1] = As[ks + tig][rb + 8];
                a[mi][2] = As[ks + tig + 4][rb];
                a[mi][3] = As[ks + tig + 4][rb + 8];
            }
#pragma unroll
            for (int ni = 0; ni < 4; ni++) {
                const int nb = wnn + ni * 8 + grp;
                b[ni][0] = Ws[ks + tig][nb];
                b[ni][1] = Ws[ks + tig + 4][nb];
            }
#pragma unroll
            for (int mi = 0; mi < 4; mi++)
#pragma unroll
                for (int ni = 0; ni < 4; ni++)
                    mma_tf32(c[mi][ni], a[mi], b[ni]);
        }
        __syncthreads();
    }

#pragma unroll
    for (int ni = 0; ni < 4; ni++) {
        const int col = n0 + wnn + ni * 8 + tig * 2;
        float bias0 = b1[col], bias1 = b1[col + 1];
        if (b2) { bias0 += b2[col]; bias1 += b2[col + 1]; }
#pragma unroll
        for (int mi = 0; mi < 4; mi++) {
            const int row = m0 + wm + mi * 16 + grp;
            C[(size_t)row * N + col]           = c[mi][ni][0] + bias0;
            C[(size_t)row * N + col + 1]       = c[mi][ni][1] + bias1;
            C[(size_t)(row + 8) * N + col]     = c[mi][ni][2] + bias0;
            C[(size_t)(row + 8) * N + col + 1] = c[mi][ni][3] + bias1;
        }
    }
}

__global__ void __launch_bounds__(256)
mma_gemm_nt(const float* __restrict__ A, const float* __restrict__ W,
            const float* __restrict__ b1, const float* __restrict__ b2,
            float* __restrict__ C, int N, int K)
{
    __shared__ uint32_t As[16][136];
    __shared__ uint32_t Ws[16][136];
    gemm_body(A, W, b1, b2, C, N, K, As, Ws);
}

__global__ void __launch_bounds__(256)
mma_gemm_qkv(const float* __restrict__ A,
             const float* __restrict__ Wq, const float* __restrict__ Wk, const float* __restrict__ Wv,
             const float* __restrict__ bq, const float* __restrict__ bk, const float* __restrict__ bv,
             float* __restrict__ Oq, float* __restrict__ Ok, float* __restrict__ Ov)
{
    __shared__ uint32_t As[16][136];
    __shared__ uint32_t Ws[16][136];
    const int z = blockIdx.z;
    const float* W = (z == 0) ? Wq : (z == 1) ? Wk : Wv;
    const float* b = (z == 0) ? bq : (z == 1) ? bk : bv;
    float* O       = (z == 0) ? Oq : (z == 1) ? Ok : Ov;
    gemm_body(A, W, b, nullptr, O, HH, HH, As, Ws);
}

// =====================================================================
// Persistent LSTM: split-bf16 mma, counter barrier, 4-chunk cp.async.
// =====================================================================
__global__ void __launch_bounds__(128, 1)
lstm_kernel(const float* __restrict__ Whh)
{
    extern __shared__ char smraw[];
    __nv_bfloat16* Whi = (__nv_bfloat16*)smraw;
    __nv_bfloat16* Wlo = Whi + 32 * WSTRIDE;
    __nv_bfloat16* hhi = Wlo + 32 * WSTRIDE;
    __nv_bfloat16* hlo = hhi + 16 * WSTRIDE;
    float* gbuf = (float*)(hlo + 16 * WSTRIDE);
    float* cst  = gbuf + 32 * 17;

    const int tid = threadIdx.x;
    const int cta = blockIdx.x;
    const int lane = tid & 31, warp = tid >> 5;
    const int grp = lane >> 2, tig = lane & 3;

    // one-time: split W_hh slice into bf16 hi/lo in SMEM
    for (int i = tid; i < 32 * 1024; i += 128) {
        const int r = i >> 10, k = i & 1023;
        const int jrow = (r >> 3) * 1024 + cta * UPC + (r & 7);
        __nv_bfloat16 hi, lo;
        bsplit(Whh[(size_t)jrow * HH + k], hi, lo);
        Whi[r * WSTRIDE + k] = hi;
        Wlo[r * WSTRIDE + k] = lo;
    }
    cst[tid] = 0.f;
    __syncthreads();

    const uint32_t a_row = lane & 15;
    const uint32_t a_colB = (lane >> 4) * 16;
    const uint32_t ahi0 = smem_u32(hhi) + a_row * (WSTRIDE * 2) + a_colB;
    const uint32_t alo0 = smem_u32(hlo) + a_row * (WSTRIDE * 2) + a_colB;
    const uint32_t b_row = warp * 8 + (lane & 7);
    const uint32_t b_colB = ((lane >> 3) & 1) * 16;
    const uint32_t bhi0 = smem_u32(Whi) + b_row * (WSTRIDE * 2) + b_colB;
    const uint32_t blo0 = smem_u32(Wlo) + b_row * (WSTRIDE * 2) + b_colB;
    const uint32_t s_hhi = smem_u32(hhi), s_hlo = smem_u32(hlo);

    const int r0 = warp * 8 + tig * 2;
    const int jrow0 = warp * 1024 + cta * UPC + tig * 2;
    const int su = tid & 7, sb = tid >> 3;
    const int unit = cta * UPC + su;
    int* mycnt = &g_cnt[(cta & 3) * 32];

    for (int t = 0; t < SS; t++) {
        // barrier-independent prefetch of input-gate contributions
        const float2 gt0 = *(const float2*)(g_gates + ((size_t)grp       * SS + t) * HX4 + jrow0);
        const float2 gt1 = *(const float2*)(g_gates + ((size_t)(grp + 8) * SS + t) * HX4 + jrow0);

        float c[4] = {0.f, 0.f, 0.f, 0.f};
        if (t > 0) {
            // grid barrier: 4 group counters, each must reach 32*t
            if (lane < 4) {
                const int tgt = 32 * t;
                while (ld_acq(&g_cnt[lane * 32]) < tgt) { }
            }
            __syncwarp();
            __syncthreads();

            // stage h_{t-1} in 4 pipelined chunks via cp.async
            const __nv_bfloat16* shi = g_hhi[t & 1];
            const __nv_bfloat16* slo = g_hlo[t & 1];
#pragma unroll
            for (int ph = 0; ph < 4; ph++) {
#pragma unroll
                for (int i2 = 0; i2 < 4; i2++) {
                    const int i = tid + i2 * 128;                  // 0..511
                    const int row = i >> 5;
                    const int col = ph * 256 + (i & 31) * 8;
                    cp16(s_hhi + row * (WSTRIDE * 2) + col * 2, shi + row * 1024 + col);
                    cp16(s_hlo + row * (WSTRIDE * 2) + col * 2, slo + row * 1024 + col);
                }
                CP_COMMIT();
            }

            CP_WAIT(3); __syncthreads();
#pragma unroll 4
            for (int kt = 0; kt < 16; kt++) {
                const uint32_t off = kt * 32;
                uint32_t ah[4], al[4], bh[2], bl[2];
                ldsm_x4(ah, ahi0 + off); ldsm_x4(al, alo0 + off);
                ldsm_x2(bh, bhi0 + off); ldsm_x2(bl, blo0 + off);
                mma_bf16(c, ah, bh); mma_bf16(c, al, bh); mma_bf16(c, ah, bl);
            }
            CP_WAIT(2); __syncthreads();
#pragma unroll 4
            for (int kt = 16; kt < 32; kt++) {
                const uint32_t off = kt * 32;
                uint32_t ah[4], al[4], bh[2], bl[2];
                ldsm_x4(ah, ahi0 + off); ldsm_x4(al, alo0 + off);
                ldsm_x2(bh, bhi0 + off); ldsm_x2(bl, blo0 + off);
                mma_bf16(c, ah, bh); mma_bf16(c, al, bh); mma_bf16(c, ah, bl);
            }
            CP_WAIT(1); __syncthreads();
#pragma unroll 4
            for (int kt = 32; kt < 48; kt++) {
                const uint32_t off = kt * 32;
                uint32_t ah[4], al[4], bh[2], bl[2];
                ldsm_x4(ah, ahi0 + off); ldsm_x4(al, alo0 + off);
                ldsm_x2(bh, bhi0 + off); ldsm_x2(bl, blo0 + off);
                mma_bf16(c, ah, bh); mma_bf16(c, al, bh); mma_bf16(c, ah, bl);
            }
            CP_WAIT(0); __syncthreads();
#pragma unroll 4
            for (int kt = 48; kt < 64; kt++) {
                const uint32_t off = kt * 32;
                uint32_t ah[4], al[4], bh[2], bl[2];
                ldsm_x4(ah, ahi0 + off); ldsm_x4(al, alo0 + off);
                ldsm_x2(bh, bhi0 + off); ldsm_x2(bl, blo0 + off);
                mma_bf16(c, ah, bh); mma_bf16(c, al, bh); mma_bf16(c, ah, bl);
            }
        }

        gbuf[(r0    ) * 17 + grp    ] = c[0] + gt0.x;
        gbuf[(r0 + 1) * 17 + grp    ] = c[1] + gt0.y;
        gbuf[(r0    ) * 17 + grp + 8] = c[2] + gt1.x;
        gbuf[(r0 + 1) * 17 + grp + 8] = c[3] + gt1.y;
        __syncthreads();

        float h;
        {
            const float iv = gbuf[(0 * 8 + su) * 17 + sb];
            const float fv = gbuf[(1 * 8 + su) * 17 + sb];
            const float gv = gbuf[(2 * 8 + su) * 17 + sb];
            const float ov = gbuf[(3 * 8 + su) * 17 + sb];
            const float ig = 1.f / (1.f + expf(-iv));
            const float fg = 1.f / (1.f + expf(-fv));
            const float og = 1.f / (1.f + expf(-ov));
            const float cv = fg * cst[tid] + ig * tanhf(gv);
            cst[tid] = cv;
            h = og * tanhf(cv);
            __nv_bfloat16 hi, lo;
            bsplit(h, hi, lo);
            g_hhi[(t + 1) & 1][sb * HH + unit] = hi;
            g_hlo[(t + 1) & 1][sb * HH + unit] = lo;
        }
        __syncthreads();                         // all h stores done CTA-wide
        if (tid == 0) red_add_release(mycnt, 1); // release-cumulative publish
        g_enc[((size_t)sb * SS + t) * HH + unit] = h;   // off the critical path
    }
}

// ============ block reduction helper (256 threads) ============
__device__ __forceinline__ float blk_sum256(float v, float* red)
{
#pragma unroll
    for (int o = 16; o > 0; o >>= 1) v += __shfl_down_sync(0xffffffffu, v, o);
    const int tid = threadIdx.x;
    if ((tid & 31) == 0) red[tid >> 5] = v;
    __syncthreads();
    if (tid < 32) {
        float x = (tid < 8) ? red[tid] : 0.f;
#pragma unroll
        for (int o = 4; o > 0; o >>= 1) x += __shfl_down_sync(0xffffffffu, x, o);
        if (tid == 0) red[0] = x;
    }
    __syncthreads();
    const float s = red[0];
    __syncthreads();
    return s;
}

// ============ span mean-pool + LayerNorm ============
__global__ void pool_ln_kernel(const float* __restrict__ gamma, const float* __restrict__ beta,
                               const int* __restrict__ heads, const int* __restrict__ tails)
{
    __shared__ float red[32];
    const int span = blockIdx.x;
    const int tid = threadIdx.x;
    const int b = span >> 5;
    const int head = heads[span], tail = tails[span];

    float4 acc = make_float4(0.f, 0.f, 0.f, 0.f);
    for (int s = head + 1; s < tail; s++) {
        const float4 v = *(const float4*)(g_enc + ((size_t)b * SS + s) * HH + tid * 4);
        acc.x += v.x; acc.y += v.y; acc.z += v.z; acc.w += v.w;
    }
    const float invc = 1.f / (float)(tail - head - 1);
    acc.x *= invc; acc.y *= invc; acc.z *= invc; acc.w *= invc;

    const float mu = blk_sum256(acc.x + acc.y + acc.z + acc.w, red) * (1.f / HH);
    const float dx = acc.x - mu, dy = acc.y - mu, dz = acc.z - mu, dw = acc.w - mu;
    const float var = blk_sum256(dx*dx + dy*dy + dz*dz + dw*dw, red) * (1.f / HH);
    const float rstd = rsqrtf(var + 1e-7f);

    const int h = tid * 4;
    const float4 gm = *(const float4*)(gamma + h);
    const float4 bt = *(const float4*)(beta + h);
    float4 o = make_float4(dx*rstd*gm.x + bt.x, dy*rstd*gm.y + bt.y,
                           dz*rstd*gm.z + bt.z, dw*rstd*gm.w + bt.w);
    *(float4*)(g_pool + (size_t)span * HH + h) = o;
}

// ============ residual LayerNorm ============
__global__ void ln_res_kernel(const float* __restrict__ gamma, const float* __restrict__ beta)
{
    __shared__ float red[32];
    const int row = blockIdx.x;
    const int tid = threadIdx.x;
    const size_t off = (size_t)row * HH + tid * 4;

    float4 x = *(const float4*)(g_wo + off);
    const float4 p = *(const float4*)(g_pool + off);
    x.x += p.x; x.y += p.y; x.z += p.z; x.w += p.w;

    const float mu = blk_sum256(x.x + x.y + x.z + x.w, red) * (1.f / HH);
    const float dx = x.x - mu, dy = x.y - mu, dz = x.z - mu, dw = x.w - mu;
    const float var = blk_sum256(dx*dx + dy*dy + dz*dz + dw*dw, red) * (1.f / HH);
    const float rstd = rsqrtf(var + 1e-7f);

    const int h = tid * 4;
    const float4 gm = *(const float4*)(gamma + h);
    const float4 bt = *(const float4*)(beta + h);
    float4 o = make_float4(dx*rstd*gm.x + bt.x, dy*rstd*gm.y + bt.y,
                           dz*rstd*gm.z + bt.z, dw*rstd*gm.w + bt.w);
    *(float4*)(g_attn + off) = o;
}

// ============ span attention: one CTA per (b, head) ============
__global__ void attn_kernel(const int* __restrict__ mask)
{
    __shared__ float Qs[32][65], Ks[32][65], Vs[32][65];
    __shared__ float P[32][33];
    __shared__ int ms[32];

    const int bh = blockIdx.x;
    const int b = bh / NHEADS, hd = bh % NHEADS;
    const int tid = threadIdx.x;
    const size_t rowbase = (size_t)b * NSPAN;
    const int col0 = hd * DHEAD;

    for (int i = tid; i < NSPAN * DHEAD; i += 128) {
        const int n = i >> 6, d = i & 63;
        const size_t off = (rowbase + n) * HH + col0 + d;
        Qs[n][d] = g_q[off];
        Ks[n][d] = g_k[off];
        Vs[n][d] = g_v[off];
    }
    if (tid < 32) ms[tid] = mask[b * NSPAN + tid];
    __syncthreads();

    for (int i = tid; i < 1024; i += 128) {
        const int qi = i >> 5, kj = i & 31;
        float s = 0.f;
#pragma unroll
        for (int d = 0; d < 64; d++) s += Qs[qi][d] * Ks[kj][d];
        s *= 0.125f;
        P[qi][kj] = (ms[qi] && ms[kj]) ? s : -3.402823466e38f;
    }
    __syncthreads();

    if (tid < 32) {
        float mx = -3.402823466e38f;
#pragma unroll
        for (int j = 0; j < 32; j++) mx = fmaxf(mx, P[tid][j]);
        float sum = 0.f;
#pragma unroll
        for (int j = 0; j < 32; j++) { float e = expf(P[tid][j] - mx); P[tid][j] = e; sum += e; }
        const float inv = 1.f / sum;
#pragma unroll
        for (int j = 0; j < 32; j++) P[tid][j] = (ms[tid] && ms[j]) ? P[tid][j] * inv : 0.f;
    }
    __syncthreads();

    for (int i = tid; i < NSPAN * DHEAD; i += 128) {
        const int qi = i >> 6, d = i & 63;
        float s = 0.f;
#pragma unroll
        for (int j = 0; j < 32; j++) s += P[qi][j] * Vs[j][d];
        g_ctx[(rowbase + qi) * HH + col0 + d] = s;
    }
}

// ============ classifier: warp per row, N=5 ============
__global__ void __launch_bounds__(256)
clf_kernel(const float* __restrict__ W, const float* __restrict__ b, float* __restrict__ out)
{
    __shared__ float ws[NCLS * HH];
    const int tid = threadIdx.x;
    for (int i = tid; i < NCLS * HH; i += 256) ws[i] = W[i];
    __syncthreads();

    const int warp = tid >> 5, lane = tid & 31;
    const int row = blockIdx.x * 8 + warp;
    const float* a = g_attn + (size_t)row * HH;

    float acc[NCLS] = {0.f, 0.f, 0.f, 0.f, 0.f};
    for (int k = lane; k < HH; k += 32) {
        const float av = a[k];
#pragma unroll
        for (int c = 0; c < NCLS; c++) acc[c] += av * ws[c * HH + k];
    }
#pragma unroll
    for (int c = 0; c < NCLS; c++) {
#pragma unroll
        for (int o = 16; o > 0; o >>= 1) acc[c] += __shfl_down_sync(0xffffffffu, acc[c], o);
    }
    if (lane == 0) {
#pragma unroll
        for (int c = 0; c < NCLS; c++) out[(size_t)row * NCLS + c] = acc[c] + b[c];
    }
}

// ============ launch ============
extern "C" void kernel_launch(void* const* d_in, const int* in_sizes, int n_in,
                              void* d_out, int out_size)
{
    const float* enc_in  = (const float*)d_in[0];
    const float* W_ih    = (const float*)d_in[1];
    const float* W_hh    = (const float*)d_in[2];
    const float* b_ih    = (const float*)d_in[3];
    const float* b_hh    = (const float*)d_in[4];
    const float* ln_g    = (const float*)d_in[5];
    const float* ln_b    = (const float*)d_in[6];
    const float* Wq      = (const float*)d_in[7];
    const float* bq      = (const float*)d_in[8];
    const float* Wk      = (const float*)d_in[9];
    const float* bk      = (const float*)d_in[10];
    const float* Wv      = (const float*)d_in[11];
    const float* bv      = (const float*)d_in[12];
    const float* Wo      = (const float*)d_in[13];
    const float* bo      = (const float*)d_in[14];
    const float* aln_g   = (const float*)d_in[15];
    const float* aln_b   = (const float*)d_in[16];
    const float* clf_W   = (const float*)d_in[17];
    const float* clf_b   = (const float*)d_in[18];
    const int*   heads   = (const int*)d_in[19];
    const int*   tails   = (const int*)d_in[20];
    const int*   mask    = (const int*)d_in[21];
    float* out = (float*)d_out;

    float *gates, *pool, *q, *k, *v, *ctx, *wo_buf;
    cudaGetSymbolAddress((void**)&gates,  g_gates);
    cudaGetSymbolAddress((void**)&pool,   g_pool);
    cudaGetSymbolAddress((void**)&q,      g_q);
    cudaGetSymbolAddress((void**)&k,      g_k);
    cudaGetSymbolAddress((void**)&v,      g_v);
    cudaGetSymbolAddress((void**)&ctx,    g_ctx);
    cudaGetSymbolAddress((void**)&wo_buf, g_wo);

    // 0. reset barrier counters (deterministic across graph replays)
    reset_kernel<<<1, 32>>>();

    // 1. gates = X @ W_ih^T + b_ih + b_hh   (tf32, pipelined)
    mma_gemm_nt<<<dim3(HX4 / 128, (BB * SS) / 128), 256>>>(
        enc_in, W_ih, b_ih, b_hh, gates, HX4, HH);

    // 2. persistent LSTM
    const int smem = (32 * WSTRIDE * 2 + 16 * WSTRIDE * 2) * (int)sizeof(__nv_bfloat16)
                   + (32 * 17 + 128) * (int)sizeof(float);
    cudaFuncSetAttribute(lstm_kernel, cudaFuncAttributeMaxDynamicSharedMemorySize, smem);
    lstm_kernel<<<NCTA, 128, smem>>>(W_hh);

    // 3. span pool + LN
    pool_ln_kernel<<<BB * NSPAN, 256>>>(ln_g, ln_b, heads, tails);

    // 4. fused QKV projections (tf32)
    mma_gemm_qkv<<<dim3(HH / 128, (BB * NSPAN) / 128, 3), 256>>>(
        pool, Wq, Wk, Wv, bq, bk, bv, q, k, v);

    // 5. attention
    attn_kernel<<<BB * NHEADS, 128>>>(mask);

    // 6. output projection (tf32)
    mma_gemm_nt<<<dim3(HH / 128, (BB * NSPAN) / 128), 256>>>(ctx, Wo, bo, nullptr, wo_buf, HH, HH);

    // 7. residual LN
    ln_res_kernel<<<BB * NSPAN, 256>>>(aln_g, aln_b);

    // 8. classifier -> d_out [B,NS,L]
    clf_kernel<<<(BB * NSPAN) / 8, 256>>>(clf_W, clf_b, out);
}

// round 8
// speedup vs baseline: 2.6810x; 1.0546x over previous
#include <cuda_runtime.h>
#include <cuda_bf16.h>
#include <math.h>
#include <stdint.h>

#define BB      16
#define SS      1024
#define HH      1024
#define HX4     4096
#define NSPAN   32
#define NHEADS  16
#define DHEAD   64
#define NCLS    5
#define NCTA    128
#define UPC     8
#define WSTRIDE 1032   // padded bf16 row stride -> conflict-free ldmatrix

// ---------------- device scratch ----------------
__device__ float g_gates[(size_t)BB * SS * HX4];
__device__ float g_enc  [(size_t)BB * SS * HH];
__device__ __nv_bfloat16 g_hhi[2][BB * HH];
__device__ __nv_bfloat16 g_hlo[2][BB * HH];
__device__ int g_cnt[4 * 32];                 // 4 counters, 128B apart
__device__ float g_pool [BB * NSPAN * HH];
__device__ float g_q    [BB * NSPAN * HH];
__device__ float g_k    [BB * NSPAN * HH];
__device__ float g_v    [BB * NSPAN * HH];
__device__ float g_ctx  [BB * NSPAN * HH];
__device__ float g_wo   [BB * NSPAN * HH];
__device__ float g_attn [BB * NSPAN * HH];

// ---------------- asm helpers ----------------
__device__ __forceinline__ uint32_t f2tf32(float x) {
    uint32_t r; asm("cvt.rna.tf32.f32 %0, %1;" : "=r"(r) : "f"(x)); return r;
}
__device__ __forceinline__ void mma_tf32(float* c, const uint32_t* a, const uint32_t* b) {
    asm volatile("mma.sync.aligned.m16n8k8.row.col.f32.tf32.tf32.f32 "
        "{%0,%1,%2,%3}, {%4,%5,%6,%7}, {%8,%9}, {%0,%1,%2,%3};"
        : "+f"(c[0]), "+f"(c[1]), "+f"(c[2]), "+f"(c[3])
        : "r"(a[0]), "r"(a[1]), "r"(a[2]), "r"(a[3]), "r"(b[0]), "r"(b[1]));
}
__device__ __forceinline__ void mma_bf16(float* c, const uint32_t* a, const uint32_t* b) {
    asm volatile("mma.sync.aligned.m16n8k16.row.col.f32.bf16.bf16.f32 "
        "{%0,%1,%2,%3}, {%4,%5,%6,%7}, {%8,%9}, {%0,%1,%2,%3};"
        : "+f"(c[0]), "+f"(c[1]), "+f"(c[2]), "+f"(c[3])
        : "r"(a[0]), "r"(a[1]), "r"(a[2]), "r"(a[3]), "r"(b[0]), "r"(b[1]));
}
__device__ __forceinline__ void ldsm_x4(uint32_t* r, uint32_t addr) {
    asm volatile("ldmatrix.sync.aligned.m8n8.x4.shared.b16 {%0,%1,%2,%3}, [%4];"
        : "=r"(r[0]), "=r"(r[1]), "=r"(r[2]), "=r"(r[3]) : "r"(addr));
}
__device__ __forceinline__ uint32_t smem_u32(const void* p) {
    uint32_t a;
    asm("{ .reg .u64 t; cvta.to.shared.u64 t, %1; cvt.u32.u64 %0, t; }" : "=r"(a) : "l"(p));
    return a;
}
__device__ __forceinline__ void bsplit(float w, __nv_bfloat16& hi, __nv_bfloat16& lo) {
    hi = __float2bfloat16(w);
    lo = __float2bfloat16(w - __bfloat162float(hi));
}
__device__ __forceinline__ int ld_acq(const int* p) {
    int v; asm volatile("ld.acquire.gpu.global.b32 %0, [%1];" : "=r"(v) : "l"(p)); return v;
}
__device__ __forceinline__ void red_add_release(int* p, int v) {
    asm volatile("red.release.gpu.global.add.s32 [%0], %1;" :: "l"(p), "r"(v) : "memory");
}
__device__ __forceinline__ void cp16(uint32_t s, const void* g) {
    asm volatile("cp.async.cg.shared.global [%0], [%1], 16;" :: "r"(s), "l"(g));
}
#define CP_COMMIT() asm volatile("cp.async.commit_group;" ::: "memory")
#define CP_WAIT(n)  asm volatile("cp.async.wait_group %0;" :: "n"(n) : "memory")

__global__ void reset_kernel()
{
    if (threadIdx.x < 4) g_cnt[threadIdx.x * 32] = 0;
}

// =====================================================================
// tf32 tensor-core GEMM body (software-pipelined k-slabs).
// =====================================================================
__device__ __forceinline__ void gemm_body(
    const float* __restrict__ A, const float* __restrict__ W,
    const float* __restrict__ b1, const float* __restrict__ b2,
    float* __restrict__ C, int N, int K,
    uint32_t (*As)[136], uint32_t (*Ws)[136])
{
    const int tid = threadIdx.x;
    const int lane = tid & 31, warp = tid >> 5;
    const int wm = (warp >> 2) * 64;
    const int wnn = (warp & 3) * 32;
    const int tig = lane & 3, grp = lane >> 2;

    const int n0 = blockIdx.x * 128, m0 = blockIdx.y * 128;
    const int lr = tid >> 1;
    const int kq = (tid & 1) * 8;

    float c[4][4][4];
#pragma unroll
    for (int mi = 0; mi < 4; mi++)
#pragma unroll
        for (int ni = 0; ni < 4; ni++)
#pragma unroll
            for (int j = 0; j < 4; j++) c[mi][ni][j] = 0.f;

    const float* Ap = A + (size_t)(m0 + lr) * K + kq;
    const float* Wp = W + (size_t)(n0 + lr) * K + kq;

    float4 av0 = *(const float4*)(Ap);
    float4 av1 = *(const float4*)(Ap + 4);
    float4 wv0 = *(const float4*)(Wp);
    float4 wv1 = *(const float4*)(Wp + 4);

    for (int k0 = 0; k0 < K; k0 += 16) {
        As[kq+0][lr] = f2tf32(av0.x); As[kq+1][lr] = f2tf32(av0.y);
        As[kq+2][lr] = f2tf32(av0.z); As[kq+3][lr] = f2tf32(av0.w);
        As[kq+4][lr] = f2tf32(av1.x); As[kq+5][lr] = f2tf32(av1.y);
        As[kq+6][lr] = f2tf32(av1.z); As[kq+7][lr] = f2tf32(av1.w);
        Ws[kq+0][lr] = f2tf32(wv0.x); Ws[kq+1][lr] = f2tf32(wv0.y);
        Ws[kq+2][lr] = f2tf32(wv0.z); Ws[kq+3][lr] = f2tf32(wv0.w);
        Ws[kq+4][lr] = f2tf32(wv1.x); Ws[kq+5][lr] = f2tf32(wv1.y);
        Ws[kq+6][lr] = f2tf32(wv1.z); Ws[kq+7][lr] = f2tf32(wv1.w);
        __syncthreads();

        if (k0 + 16 < K) {
            av0 = *(const float4*)(Ap + k0 + 16);
            av1 = *(const float4*)(Ap + k0 + 20);
            wv0 = *(const float4*)(Wp + k0 + 16);
            wv1 = *(const float4*)(Wp + k0 + 20);
        }

#pragma unroll
        for (int ks = 0; ks < 16; ks += 8) {
            uint32_t a[4][4], b[4][2];
#pragma unroll
            for (int mi = 0; mi < 4; mi++) {
                const int rb = wm + mi * 16 + grp;
                a[mi][0] = As[ks + tig][rb];
                a[mi][1] = As[ks + tig][rb + 8];
                a[mi][2] = As[ks + tig + 4][rb];
                a[mi][3] = As[ks + tig + 4][rb + 8];
            }
#pragma unroll
            for (int ni = 0; ni < 4; ni++) {
                const int nb = wnn + ni * 8 + grp;
                b[ni][0] = Ws[ks + tig][nb];
                b[ni][1] = Ws[ks + tig + 4][nb];
            }
#pragma unroll
            for (int mi = 0; mi < 4; mi++)
#pragma unroll
                for (int ni = 0; ni < 4; ni++)
                    mma_tf32(c[mi][ni], a[mi], b[ni]);
        }
        __syncthreads();
    }

#pragma unroll
    for (int ni = 0; ni < 4; ni++) {
        const int col = n0 + wnn + ni * 8 + tig * 2;
        float bias0 = b1[col], bias1 = b1[col + 1];
        if (b2) { bias0 += b2[col]; bias1 += b2[col + 1]; }
#pragma unroll
        for (int mi = 0; mi < 4; mi++) {
            const int row = m0 + wm + mi * 16 + grp;
            C[(size_t)row * N + col]           = c[mi][ni][0] + bias0;
            C[(size_t)row * N + col + 1]       = c[mi][ni][1] + bias1;
            C[(size_t)(row + 8) * N + col]     = c[mi][ni][2] + bias0;
            C[(size_t)(row + 8) * N + col + 1] = c[mi][ni][3] + bias1;
        }
    }
}

__global__ void __launch_bounds__(256)
mma_gemm_nt(const float* __restrict__ A, const float* __restrict__ W,
            const float* __restrict__ b1, const float* __restrict__ b2,
            float* __restrict__ C, int N, int K)
{
    __shared__ uint32_t As[16][136];
    __shared__ uint32_t Ws[16][136];
    gemm_body(A, W, b1, b2, C, N, K, As, Ws);
}

__global__ void __launch_bounds__(256)
mma_gemm_qkv(const float* __restrict__ A,
             const float* __restrict__ Wq, const float* __restrict__ Wk, const float* __restrict__ Wv,
             const float* __restrict__ bq, const float* __restrict__ bk, const float* __restrict__ bv,
             float* __restrict__ Oq, float* __restrict__ Ok, float* __restrict__ Ov)
{
    __shared__ uint32_t As[16][136];
    __shared__ uint32_t Ws[16][136];
    const int z = blockIdx.z;
    const float* W = (z == 0) ? Wq : (z == 1) ? Wk : Wv;
    const float* b = (z == 0) ? bq : (z == 1) ? bk : bv;
    float* O       = (z == 0) ? Oq : (z == 1) ? Ok : Ov;
    gemm_body(A, W, b, nullptr, O, HH, HH, As, Ws);
}

// =====================================================================
// Persistent LSTM: split-bf16 mma, 8 warps (2/SMSP), k-split per warp.
// Warp w: gate rows (w>>1)*8..+8, k-half (w&1)*512..+512 (32 k-tiles).
// Partial sums in gbuf[2][32][17]; pointwise adds the two planes.
// =====================================================================
__global__ void __launch_bounds__(256, 1)
lstm_kernel(const float* __restrict__ Whh)
{
    extern __shared__ char smraw[];
    __nv_bfloat16* Whi = (__nv_bfloat16*)smraw;
    __nv_bfloat16* Wlo = Whi + 32 * WSTRIDE;
    __nv_bfloat16* hhi = Wlo + 32 * WSTRIDE;
    __nv_bfloat16* hlo = hhi + 16 * WSTRIDE;
    float* gbuf = (float*)(hlo + 16 * WSTRIDE);     // [2][32][17]
    float* cst  = gbuf + 2 * 32 * 17;               // [128]

    const int tid = threadIdx.x;
    const int cta = blockIdx.x;
    const int lane = tid & 31, warp = tid >> 5;
    const int grp = lane >> 2, tig = lane & 3;
    const int gate = warp >> 1;                     // 0..3
    const int khalf = warp & 1;                     // 0/1

    // one-time: split W_hh slice into bf16 hi/lo in SMEM
    for (int i = tid; i < 32 * 1024; i += 256) {
        const int r = i >> 10, k = i & 1023;
        const int jrow = (r >> 3) * 1024 + cta * UPC + (r & 7);
        __nv_bfloat16 hi, lo;
        bsplit(Whh[(size_t)jrow * HH + k], hi, lo);
        Whi[r * WSTRIDE + k] = hi;
        Wlo[r * WSTRIDE + k] = lo;
    }
    if (tid < 128) cst[tid] = 0.f;
    __syncthreads();

    // ldmatrix lane addresses (A: h hi / lo; B: merged Whi|Wlo x4)
    const uint32_t s_hhi = smem_u32(hhi), s_hlo = smem_u32(hlo);
    const uint32_t khB = (uint32_t)khalf * 1024;    // 512 bf16 = 1024 B
    const uint32_t a_row = lane & 15;
    const uint32_t a_colB = (lane >> 4) * 16;
    const uint32_t ahi0 = s_hhi + a_row * (WSTRIDE * 2) + a_colB + khB;
    const uint32_t alo0 = s_hlo + a_row * (WSTRIDE * 2) + a_colB + khB;
    const uint32_t brow = (uint32_t)gate * 8 + (lane & 7);
    const uint32_t bsel = (lane < 16) ? smem_u32(Whi) : smem_u32(Wlo);
    const uint32_t b0 = bsel + brow * (WSTRIDE * 2) + ((lane >> 3) & 1) * 16 + khB;

    const int r0 = gate * 8 + tig * 2;
    const int jrow0 = gate * 1024 + cta * UPC + tig * 2;
    const int su = tid & 7, sb = tid >> 3;          // valid for tid<128
    const int unit = cta * UPC + su;
    int* mycnt = &g_cnt[(cta & 3) * 32];
    float* gplane = gbuf + khalf * (32 * 17);

    // staging phase column bases (k-interleaved so both k-half warp
    // groups start after the first wait)
    const int phcol[4] = {0, 512, 256, 768};

    for (int t = 0; t < SS; t++) {
        // barrier-independent prefetch of input-gate contributions (even-k warps only)
        float2 gt0 = make_float2(0.f, 0.f), gt1 = make_float2(0.f, 0.f);
        if (khalf == 0) {
            gt0 = *(const float2*)(g_gates + ((size_t)grp       * SS + t) * HX4 + jrow0);
            gt1 = *(const float2*)(g_gates + ((size_t)(grp + 8) * SS + t) * HX4 + jrow0);
        }

        float c[4] = {0.f, 0.f, 0.f, 0.f};
        if (t > 0) {
            // grid barrier
            if (warp == 0 && lane < 4) {
                const int tgt = 32 * t;
                while (ld_acq(&g_cnt[lane * 32]) < tgt) { }
            }
            __syncthreads();

            // stage h_{t-1}: 4 k-interleaved phases via cp.async
            const __nv_bfloat16* shi = g_hhi[t & 1];
            const __nv_bfloat16* slo = g_hlo[t & 1];
#pragma unroll
            for (int ph = 0; ph < 4; ph++) {
#pragma unroll
                for (int j = 0; j < 2; j++) {
                    const int i = tid + j * 256;          // 0..511
                    const int row = i >> 5;
                    const int col = phcol[ph] + (i & 31) * 8;
                    cp16(s_hhi + row * (WSTRIDE * 2) + col * 2, shi + row * 1024 + col);
                    cp16(s_hlo + row * (WSTRIDE * 2) + col * 2, slo + row * 1024 + col);
                }
                CP_COMMIT();
            }

            CP_WAIT(2); __syncthreads();    // phases 0,1 ready: both k-halves' first 16 tiles
#pragma unroll 4
            for (int kt = 0; kt < 16; kt++) {
                const uint32_t off = kt * 32;
                uint32_t ah[4], al[4], bb[4];
                ldsm_x4(ah, ahi0 + off);
                ldsm_x4(al, alo0 + off);
                ldsm_x4(bb, b0 + off);
                mma_bf16(c, ah, bb);        // hi*hi
                mma_bf16(c, al, bb);        // lo_h*hi_w
                mma_bf16(c, ah, bb + 2);    // hi_h*lo_w
            }
            CP_WAIT(0); __syncthreads();    // all phases ready
#pragma unroll 4
            for (int kt = 16; kt < 32; kt++) {
                const uint32_t off = kt * 32;
                uint32_t ah[4], al[4], bb[4];
                ldsm_x4(ah, ahi0 + off);
                ldsm_x4(al, alo0 + off);
                ldsm_x4(bb, b0 + off);
                mma_bf16(c, ah, bb);
                mma_bf16(c, al, bb);
                mma_bf16(c, ah, bb + 2);
            }
        }

        // scatter partial sums (+ input gates on plane 0)
        gplane[(r0    ) * 17 + grp    ] = c[0] + gt0.x;
        gplane[(r0 + 1) * 17 + grp    ] = c[1] + gt0.y;
        gplane[(r0    ) * 17 + grp + 8] = c[2] + gt1.x;
        gplane[(r0 + 1) * 17 + grp + 8] = c[3] + gt1.y;
        __syncthreads();

        // pointwise LSTM cell on threads 0-127
        float h = 0.f;
        if (tid < 128) {
            const float iv = gbuf[(0 * 8 + su) * 17 + sb] + gbuf[32*17 + (0 * 8 + su) * 17 + sb];
            const float fv = gbuf[(1 * 8 + su) * 17 + sb] + gbuf[32*17 + (1 * 8 + su) * 17 + sb];
            const float gv = gbuf[(2 * 8 + su) * 17 + sb] + gbuf[32*17 + (2 * 8 + su) * 17 + sb];
            const float ov = gbuf[(3 * 8 + su) * 17 + sb] + gbuf[32*17 + (3 * 8 + su) * 17 + sb];
            const float ig = 1.f / (1.f + expf(-iv));
            const float fg = 1.f / (1.f + expf(-fv));
            const float og = 1.f / (1.f + expf(-ov));
            const float cv = fg * cst[tid] + ig * tanhf(gv);
            cst[tid] = cv;
            h = og * tanhf(cv);
            __nv_bfloat16 hi, lo;
            bsplit(h, hi, lo);
            g_hhi[(t + 1) & 1][sb * HH + unit] = hi;
            g_hlo[(t + 1) & 1][sb * HH + unit] = lo;
        }
        __syncthreads();                          // all h stores done CTA-wide
        if (tid == 0) red_add_release(mycnt, 1);  // release-cumulative publish
        if (tid < 128)
            g_enc[((size_t)sb * SS + t) * HH + unit] = h;   // off critical path
    }
}

// ============ block reduction helper (256 threads) ============
__device__ __forceinline__ float blk_sum256(float v, float* red)
{
#pragma unroll
    for (int o = 16; o > 0; o >>= 1) v += __shfl_down_sync(0xffffffffu, v, o);
    const int tid = threadIdx.x;
    if ((tid & 31) == 0) red[tid >> 5] = v;
    __syncthreads();
    if (tid < 32) {
        float x = (tid < 8) ? red[tid] : 0.f;
#pragma unroll
        for (int o = 4; o > 0; o >>= 1) x += __shfl_down_sync(0xffffffffu, x, o);
        if (tid == 0) red[0] = x;
    }
    __syncthreads();
    const float s = red[0];
    __syncthreads();
    return s;
}

// ============ span mean-pool + LayerNorm ============
__global__ void pool_ln_kernel(const float* __restrict__ gamma, const float* __restrict__ beta,
                               const int* __restrict__ heads, const int* __restrict__ tails)
{
    __shared__ float red[32];
    const int span = blockIdx.x;
    const int tid = threadIdx.x;
    const int b = span >> 5;
    const int head = heads[span], tail = tails[span];

    float4 acc = make_float4(0.f, 0.f, 0.f, 0.f);
    for (int s = head + 1; s < tail; s++) {
        const float4 v = *(const float4*)(g_enc + ((size_t)b * SS + s) * HH + tid * 4);
        acc.x += v.x; acc.y += v.y; acc.z += v.z; acc.w += v.w;
    }
    const float invc = 1.f / (float)(tail - head - 1);
    acc.x *= invc; acc.y *= invc; acc.z *= invc; acc.w *= invc;

    const float mu = blk_sum256(acc.x + acc.y + acc.z + acc.w, red) * (1.f / HH);
    const float dx = acc.x - mu, dy = acc.y - mu, dz = acc.z - mu, dw = acc.w - mu;
    const float var = blk_sum256(dx*dx + dy*dy + dz*dz + dw*dw, red) * (1.f / HH);
    const float rstd = rsqrtf(var + 1e-7f);

    const int h = tid * 4;
    const float4 gm = *(const float4*)(gamma + h);
    const float4 bt = *(const float4*)(beta + h);
    float4 o = make_float4(dx*rstd*gm.x + bt.x, dy*rstd*gm.y + bt.y,
                           dz*rstd*gm.z + bt.z, dw*rstd*gm.w + bt.w);
    *(float4*)(g_pool + (size_t)span * HH + h) = o;
}

// ============ residual LayerNorm ============
__global__ void ln_res_kernel(const float* __restrict__ gamma, const float* __restrict__ beta)
{
    __shared__ float red[32];
    const int row = blockIdx.x;
    const int tid = threadIdx.x;
    const size_t off = (size_t)row * HH + tid * 4;

    float4 x = *(const float4*)(g_wo + off);
    const float4 p = *(const float4*)(g_pool + off);
    x.x += p.x; x.y += p.y; x.z += p.z; x.w += p.w;

    const float mu = blk_sum256(x.x + x.y + x.z + x.w, red) * (1.f / HH);
    const float dx = x.x - mu, dy = x.y - mu, dz = x.z - mu, dw = x.w - mu;
    const float var = blk_sum256(dx*dx + dy*dy + dz*dz + dw*dw, red) * (1.f / HH);
    const float rstd = rsqrtf(var + 1e-7f);

    const int h = tid * 4;
    const float4 gm = *(const float4*)(gamma + h);
    const float4 bt = *(const float4*)(beta + h);
    float4 o = make_float4(dx*rstd*gm.x + bt.x, dy*rstd*gm.y + bt.y,
                           dz*rstd*gm.z + bt.z, dw*rstd*gm.w + bt.w);
    *(float4*)(g_attn + off) = o;
}

// ============ span attention: one CTA per (b, head) ============
__global__ void attn_kernel(const int* __restrict__ mask)
{
    __shared__ float Qs[32][65], Ks[32][65], Vs[32][65];
    __shared__ float P[32][33];
    __shared__ int ms[32];

    const int bh = blockIdx.x;
    const int b = bh / NHEADS, hd = bh % NHEADS;
    const int tid = threadIdx.x;
    const size_t rowbase = (size_t)b * NSPAN;
    const int col0 = hd * DHEAD;

    for (int i = tid; i < NSPAN * DHEAD; i += 128) {
        const int n = i >> 6, d = i & 63;
        const size_t off = (rowbase + n) * HH + col0 + d;
        Qs[n][d] = g_q[off];
        Ks[n][d] = g_k[off];
        Vs[n][d] = g_v[off];
    }
    if (tid < 32) ms[tid] = mask[b * NSPAN + tid];
    __syncthreads();

    for (int i = tid; i < 1024; i += 128) {
        const int qi = i >> 5, kj = i & 31;
        float s = 0.f;
#pragma unroll
        for (int d = 0; d < 64; d++) s += Qs[qi][d] * Ks[kj][d];
        s *= 0.125f;
        P[qi][kj] = (ms[qi] && ms[kj]) ? s : -3.402823466e38f;
    }
    __syncthreads();

    if (tid < 32) {
        float mx = -3.402823466e38f;
#pragma unroll
        for (int j = 0; j < 32; j++) mx = fmaxf(mx, P[tid][j]);
        float sum = 0.f;
#pragma unroll
        for (int j = 0; j < 32; j++) { float e = expf(P[tid][j] - mx); P[tid][j] = e; sum += e; }
        const float inv = 1.f / sum;
#pragma unroll
        for (int j = 0; j < 32; j++) P[tid][j] = (ms[tid] && ms[j]) ? P[tid][j] * inv : 0.f;
    }
    __syncthreads();

    for (int i = tid; i < NSPAN * DHEAD; i += 128) {
        const int qi = i >> 6, d = i & 63;
        float s = 0.f;
#pragma unroll
        for (int j = 0; j < 32; j++) s += P[qi][j] * Vs[j][d];
        g_ctx[(rowbase + qi) * HH + col0 + d] = s;
    }
}

// ============ classifier: warp per row, N=5 ============
__global__ void __launch_bounds__(256)
clf_kernel(const float* __restrict__ W, const float* __restrict__ b, float* __restrict__ out)
{
    __shared__ float ws[NCLS * HH];
    const int tid = threadIdx.x;
    for (int i = tid; i < NCLS * HH; i += 256) ws[i] = W[i];
    __syncthreads();

    const int warp = tid >> 5, lane = tid & 31;
    const int row = blockIdx.x * 8 + warp;
    const float* a = g_attn + (size_t)row * HH;

    float acc[NCLS] = {0.f, 0.f, 0.f, 0.f, 0.f};
    for (int k = lane; k < HH; k += 32) {
        const float av = a[k];
#pragma unroll
        for (int c = 0; c < NCLS; c++) acc[c] += av * ws[c * HH + k];
    }
#pragma unroll
    for (int c = 0; c < NCLS; c++) {
#pragma unroll
        for (int o = 16; o > 0; o >>= 1) acc[c] += __shfl_down_sync(0xffffffffu, acc[c], o);
    }
    if (lane == 0) {
#pragma unroll
        for (int c = 0; c < NCLS; c++) out[(size_t)row * NCLS + c] = acc[c] + b[c];
    }
}

// ============ launch ============
extern "C" void kernel_launch(void* const* d_in, const int* in_sizes, int n_in,
                              void* d_out, int out_size)
{
    const float* enc_in  = (const float*)d_in[0];
    const float* W_ih    = (const float*)d_in[1];
    const float* W_hh    = (const float*)d_in[2];
    const float* b_ih    = (const float*)d_in[3];
    const float* b_hh    = (const float*)d_in[4];
    const float* ln_g    = (const float*)d_in[5];
    const float* ln_b    = (const float*)d_in[6];
    const float* Wq      = (const float*)d_in[7];
    const float* bq      = (const float*)d_in[8];
    const float* Wk      = (const float*)d_in[9];
    const float* bk      = (const float*)d_in[10];
    const float* Wv      = (const float*)d_in[11];
    const float* bv      = (const float*)d_in[12];
    const float* Wo      = (const float*)d_in[13];
    const float* bo      = (const float*)d_in[14];
    const float* aln_g   = (const float*)d_in[15];
    const float* aln_b   = (const float*)d_in[16];
    const float* clf_W   = (const float*)d_in[17];
    const float* clf_b   = (const float*)d_in[18];
    const int*   heads   = (const int*)d_in[19];
    const int*   tails   = (const int*)d_in[20];
    const int*   mask    = (const int*)d_in[21];
    float* out = (float*)d_out;

    float *gates, *pool, *q, *k, *v, *ctx, *wo_buf;
    cudaGetSymbolAddress((void**)&gates,  g_gates);
    cudaGetSymbolAddress((void**)&pool,   g_pool);
    cudaGetSymbolAddress((void**)&q,      g_q);
    cudaGetSymbolAddress((void**)&k,      g_k);
    cudaGetSymbolAddress((void**)&v,      g_v);
    cudaGetSymbolAddress((void**)&ctx,    g_ctx);
    cudaGetSymbolAddress((void**)&wo_buf, g_wo);

    // 0. reset barrier counters
    reset_kernel<<<1, 32>>>();

    // 1. gates = X @ W_ih^T + b_ih + b_hh   (tf32, pipelined)
    mma_gemm_nt<<<dim3(HX4 / 128, (BB * SS) / 128), 256>>>(
        enc_in, W_ih, b_ih, b_hh, gates, HX4, HH);

    // 2. persistent LSTM (8 warps, k-split)
    const int smem = (32 * WSTRIDE * 2 + 16 * WSTRIDE * 2) * (int)sizeof(__nv_bfloat16)
                   + (2 * 32 * 17 + 128) * (int)sizeof(float);
    cudaFuncSetAttribute(lstm_kernel, cudaFuncAttributeMaxDynamicSharedMemorySize, smem);
    lstm_kernel<<<NCTA, 256, smem>>>(W_hh);

    // 3. span pool + LN
    pool_ln_kernel<<<BB * NSPAN, 256>>>(ln_g, ln_b, heads, tails);

    // 4. fused QKV projections (tf32)
    mma_gemm_qkv<<<dim3(HH / 128, (BB * NSPAN) / 128, 3), 256>>>(
        pool, Wq, Wk, Wv, bq, bk, bv, q, k, v);

    // 5. attention
    attn_kernel<<<BB * NHEADS, 128>>>(mask);

    // 6. output projection (tf32)
    mma_gemm_nt<<<dim3(HH / 128, (BB * NSPAN) / 128), 256>>>(ctx, Wo, bo, nullptr, wo_buf, HH, HH);

    // 7. residual LN
    ln_res_kernel<<<BB * NSPAN, 256>>>(aln_g, aln_b);

    // 8. classifier -> d_out [B,NS,L]
    clf_kernel<<<(BB * NSPAN) / 8, 256>>>(clf_W, clf_b, out);
}